// round 4
// baseline (speedup 1.0000x reference)
#include <cuda_runtime.h>
#include <math.h>

#define NCTA 128
#define Bz 128
#define Lz 1024
#define Dz 256
#define Tz 32
#define BD (Bz*Dz)      /* 32768 */
#define SAS 516

// smem layout (float offsets)
#define OFF_WR 0        /* 32x516 = 16512 */
#define OFF_WW 16512    /* 16512 */
#define OFF_WC 33024    /* 8x516 = 4128 */
#define OFF_A  37152    /* 32x516 = 16512 */
#define OFF_Z  53664    /* 1024 */
#define OFF_HR 54688    /* 256 */
#define OFF_HW 54944    /* 256 */
#define OFF_RED 55200   /* 8 */
#define OFF_MASK 55208  /* 256 floats = 1024 bytes */
#define SMEM_FLOATS 55464
#define SMEM_BYTES (SMEM_FLOATS*4)

// ---------------- scratch (device globals; no allocation) ----------------
__device__ float g_hr[2*BD];
__device__ float g_hw[2*BD];
__device__ float g_m[BD];
__device__ float g_logits[BD];
__device__ unsigned g_count;
__device__ unsigned g_gen;

// ---------------- helpers ----------------
__device__ __forceinline__ float warp_sum(float v){
#pragma unroll
  for (int o=16;o;o>>=1) v += __shfl_xor_sync(0xffffffffu,v,o);
  return v;
}
__device__ __forceinline__ float block_sum(float v, float* sbuf){
  v = warp_sum(v);
  int lane = threadIdx.x & 31, w = threadIdx.x >> 5;
  __syncthreads();
  if (lane == 0) sbuf[w] = v;
  __syncthreads();
  float r = sbuf[0];
#pragma unroll
  for (int i=1;i<8;i++) r += sbuf[i];
  return r;
}
__device__ __forceinline__ float block_max(float v, float* sbuf){
#pragma unroll
  for (int o=16;o;o>>=1) v = fmaxf(v, __shfl_xor_sync(0xffffffffu,v,o));
  int lane = threadIdx.x & 31, w = threadIdx.x >> 5;
  __syncthreads();
  if (lane == 0) sbuf[w] = v;
  __syncthreads();
  float r = sbuf[0];
#pragma unroll
  for (int i=1;i<8;i++) r = fmaxf(r, sbuf[i]);
  return r;
}
__device__ __forceinline__ float sigm(float x){ return 1.f/(1.f+expf(-x)); }

// sense-reversing grid barrier (all 128 CTAs co-resident: 1 CTA/SM by smem)
__device__ __forceinline__ void grid_bar(){
  __threadfence();                // release: drain this thread's stores
  __syncthreads();
  if (threadIdx.x == 0) {
    unsigned gen = *(volatile unsigned*)&g_gen;
    unsigned prev = atomicAdd(&g_count, 1u);
    if (prev == NCTA - 1u) {
      atomicExch(&g_count, 0u);
      __threadfence();
      *(volatile unsigned*)&g_gen = gen + 1u;
    } else {
      while (*(volatile unsigned*)&g_gen == gen) { __nanosleep(64); }
    }
    __threadfence();              // acquire: CCTL.IVALL -> fresh L1
  }
  __syncthreads();
}

// ---------------- the persistent mega-kernel ----------------
__global__ __launch_bounds__(256,1) void mega(
  const float* __restrict__ emb, const float* __restrict__ hr0,
  const float* __restrict__ cr0, const float* __restrict__ hw0,
  const float* __restrict__ cw0, const float* __restrict__ M,
  const int* __restrict__ mask,
  const float* __restrict__ Wih_r, const float* __restrict__ Whh_r,
  const float* __restrict__ bih_r, const float* __restrict__ bhh_r,
  const float* __restrict__ Wc,    const float* __restrict__ bc,
  const float* __restrict__ Wih_w, const float* __restrict__ Whh_w,
  const float* __restrict__ bih_w, const float* __restrict__ bhh_w,
  float* __restrict__ out)
{
  extern __shared__ __align__(16) float sm[];
  float* sWr = sm + OFF_WR;
  float* sWw = sm + OFF_WW;
  float* sWc = sm + OFF_WC;
  float* sA  = sm + OFF_A;
  float* sZ  = sm + OFF_Z;
  float* sHr = sm + OFF_HR;
  float* sHw = sm + OFF_HW;
  float* sRed = sm + OFF_RED;
  unsigned char* sMask = (unsigned char*)(sm + OFF_MASK);

  const int tid = threadIdx.x;
  const int cta = blockIdx.x;
  const int jb = cta >> 2;          // 0..31
  const int bb = cta & 3;           // 0..3
  const int b0 = bb << 5;           // 32 batch rows
  const int d0 = jb << 3;           // 8 d-cols
  const int jc0 = jb << 3;          // 8 comp j-rows
  const int b_i = tid >> 3, d_i = tid & 7;
  const int b = b0 + b_i, d = d0 + d_i;
  const int bown = cta;             // attention-owned batch row

  // ---- one-time staging: weights, mask, biases, c registers ----
  {
    const float4* Wi = (const float4*)Wih_r;
    const float4* Wh = (const float4*)Whh_r;
    float4* W4 = (float4*)sWr;
    for (int idx = tid; idx < 4096; idx += 256) {
      int r = idx >> 7, c = idx & 127;
      int j = ((r >> 3) << 8) + d0 + (r & 7);
      W4[r*129 + c] = (c < 64) ? Wi[(size_t)j*64 + c] : Wh[(size_t)j*64 + (c-64)];
    }
  }
  {
    const float4* Wi = (const float4*)Wih_w;
    const float4* Wh = (const float4*)Whh_w;
    float4* W4 = (float4*)sWw;
    for (int idx = tid; idx < 4096; idx += 256) {
      int r = idx >> 7, c = idx & 127;
      int j = ((r >> 3) << 8) + d0 + (r & 7);
      W4[r*129 + c] = (c < 64) ? Wi[(size_t)j*64 + c] : Wh[(size_t)j*64 + (c-64)];
    }
  }
  {
    const float4* Wc4 = (const float4*)Wc;
    float4* W4 = (float4*)sWc;
    for (int idx = tid; idx < 1024; idx += 256) {
      int r = idx >> 7, c = idx & 127;
      W4[r*129 + c] = Wc4[(size_t)(jc0 + r)*128 + c];
    }
  }
  for (int l = tid; l < Lz; l += 256) sMask[l] = (unsigned char)(mask[bown*Lz + l] != 0);

  const float br0 = bih_r[d]       + bhh_r[d];
  const float br1 = bih_r[256 + d] + bhh_r[256 + d];
  const float br2 = bih_r[512 + d] + bhh_r[512 + d];
  const float br3 = bih_r[768 + d] + bhh_r[768 + d];
  const float bw0 = bih_w[d]       + bhh_w[d];
  const float bw1 = bih_w[256 + d] + bhh_w[256 + d];
  const float bw2 = bih_w[512 + d] + bhh_w[512 + d];
  const float bw3 = bih_w[768 + d] + bhh_w[768 + d];
  const float bcj = bc[jc0 + d_i];
  float cr_reg = cr0[b*Dz + d];
  float cw_reg = cw0[b*Dz + d];
  __syncthreads();

  for (int t = 0; t < Tz; t++) {
    const int cur = t & 1;
    const float* hin = (t == 0) ? hr0 : g_hr + (cur^1)*BD;
    const float* hwp = (t == 0) ? hw0 : g_hw + (cur^1)*BD;
    float* hrc = g_hr + cur*BD;
    float* hwc = g_hw + cur*BD;

    // ================= phase 1: read LSTM =================
    {
      const float4* X = (const float4*)(emb + (size_t)t*BD);
      const float4* H = (const float4*)hin;
      float4* A4 = (float4*)sA;
      for (int idx = tid; idx < 4096; idx += 256) {
        int r = idx >> 7, c = idx & 127;
        A4[r*129 + c] = (c < 64) ? X[(size_t)(b0+r)*64 + c] : H[(size_t)(b0+r)*64 + (c-64)];
      }
      __syncthreads();
      const float* Ar  = sA  + b_i*SAS;
      const float* W0p = sWr + d_i*SAS;
      const float* W1p = W0p + 8*SAS;
      const float* W2p = W0p + 16*SAS;
      const float* W3p = W0p + 24*SAS;
      float a0=0.f,a1=0.f,a2=0.f,a3=0.f;
#pragma unroll 2
      for (int k = 0; k < 512; k += 4) {
        float4 A  = *(const float4*)(Ar + k);
        float4 w0 = *(const float4*)(W0p + k);
        float4 w1 = *(const float4*)(W1p + k);
        float4 w2 = *(const float4*)(W2p + k);
        float4 w3 = *(const float4*)(W3p + k);
        a0 = fmaf(A.x,w0.x, fmaf(A.y,w0.y, fmaf(A.z,w0.z, fmaf(A.w,w0.w, a0))));
        a1 = fmaf(A.x,w1.x, fmaf(A.y,w1.y, fmaf(A.z,w1.z, fmaf(A.w,w1.w, a1))));
        a2 = fmaf(A.x,w2.x, fmaf(A.y,w2.y, fmaf(A.z,w2.z, fmaf(A.w,w2.w, a2))));
        a3 = fmaf(A.x,w3.x, fmaf(A.y,w3.y, fmaf(A.z,w3.z, fmaf(A.w,w3.w, a3))));
      }
      float ig = sigm(a0 + br0);
      float fg = sigm(a1 + br1);
      float gg = tanhf(a2 + br2);
      float og = sigm(a3 + br3);
      cr_reg = fmaf(fg, cr_reg, ig*gg);
      hrc[b*Dz + d] = og * tanhf(cr_reg);
    }
    grid_bar();

    // ================= phase 2: attention (b = cta) =================
    if (t == 0) {
      sHr[tid] = hrc[bown*Dz + tid];
      __syncthreads();
      const int w = tid >> 5, lane = tid & 31;
      for (int l = w; l < Lz; l += 8) {
        const float* Mr = M + ((size_t)bown*Lz + l)*Dz;
        float s = 0.f;
#pragma unroll
        for (int u = 0; u < 8; u++) s = fmaf(Mr[lane + (u<<5)], sHr[lane + (u<<5)], s);
        s = warp_sum(s);
        if (lane == 0) sZ[l] = s;
      }
      __syncthreads();
      float raw[4]; float lmax = -INFINITY;
#pragma unroll
      for (int u = 0; u < 4; u++) {
        int l = tid + (u << 8);
        raw[u] = sMask[l] ? -INFINITY : sZ[l];
        lmax = fmaxf(lmax, raw[u]);
      }
      float gmax = block_max(lmax, sRed);
      float e[4]; float lsum = 0.f;
#pragma unroll
      for (int u = 0; u < 4; u++) { e[u] = expf(raw[u] - gmax); lsum += e[u]; }
      float gsum = block_sum(lsum, sRed);
      float inv = 1.f / gsum;
      __syncthreads();
#pragma unroll
      for (int u = 0; u < 4; u++) sZ[tid + (u << 8)] = e[u]*inv;
      __syncthreads();
      // pass 2: m = sum_l z_l * M[b,l,:], 4-way L-split, float4 over d
      const int q = tid >> 6, dq = tid & 63;
      const float4* M4 = (const float4*)M;
      float4 acc = make_float4(0.f,0.f,0.f,0.f);
      const int lb = q << 8;
#pragma unroll 4
      for (int l = lb; l < lb + 256; l++) {
        float zv = sZ[l];
        float4 Mv = M4[((size_t)bown*Lz + l)*64 + dq];
        acc.x = fmaf(zv, Mv.x, acc.x);
        acc.y = fmaf(zv, Mv.y, acc.y);
        acc.z = fmaf(zv, Mv.z, acc.z);
        acc.w = fmaf(zv, Mv.w, acc.w);
      }
      ((float4*)sA)[q*64 + dq] = acc;
      __syncthreads();
      g_m[bown*Dz + tid] = sA[tid] + sA[256 + tid] + sA[512 + tid] + sA[768 + tid];
    } else {
      sHr[tid] = hrc[bown*Dz + tid];
      sHw[tid] = hwp[bown*Dz + tid];
      __syncthreads();
      float hrv = sHr[tid], hwv = sHw[tid];
      float Shr = block_sum(hrv, sRed);
      float dot = block_sum(hrv*hwv, sRed);
      float alpha = dot - Shr;
      float zp[4], raw[4]; float lmax = -INFINITY;
#pragma unroll
      for (int u = 0; u < 4; u++) {
        int l = tid + (u << 8);
        zp[u] = sZ[l];
        raw[u] = sMask[l] ? -INFINITY : fmaf(zp[u], alpha, Shr);
        lmax = fmaxf(lmax, raw[u]);
      }
      float gmax = block_max(lmax, sRed);
      float e[4]; float lsum = 0.f, lt = 0.f;
#pragma unroll
      for (int u = 0; u < 4; u++) { e[u] = expf(raw[u] - gmax); lsum += e[u]; lt += e[u]*zp[u]; }
      float gsum = block_sum(lsum, sRed);
      float gt   = block_sum(lt,   sRed);
      float inv = 1.f / gsum;
      __syncthreads();
#pragma unroll
      for (int u = 0; u < 4; u++) sZ[tid + (u << 8)] = e[u]*inv;
      float S = gt * inv;
      g_m[bown*Dz + tid] = (1.f - S) + hwv*S;
    }
    grid_bar();

    // ================= phase 3: comp logits =================
    {
      const float4* Hc = (const float4*)hrc;
      const float4* Mm = (const float4*)g_m;
      float4* A4 = (float4*)sA;
      for (int idx = tid; idx < 4096; idx += 256) {
        int r = idx >> 7, c = idx & 127;
        A4[r*129 + c] = (c < 64) ? Hc[(size_t)(b0+r)*64 + c] : Mm[(size_t)(b0+r)*64 + (c-64)];
      }
      __syncthreads();
      const float* Ar = sA  + b_i*SAS;
      const float* Wp = sWc + d_i*SAS;
      float p0 = 0.f, p1 = 0.f;
#pragma unroll 4
      for (int k = 0; k < 512; k += 8) {
        float4 A  = *(const float4*)(Ar + k);
        float4 Wv = *(const float4*)(Wp + k);
        p0 = fmaf(A.x,Wv.x, fmaf(A.y,Wv.y, fmaf(A.z,Wv.z, fmaf(A.w,Wv.w, p0))));
        float4 A2 = *(const float4*)(Ar + k + 4);
        float4 W2 = *(const float4*)(Wp + k + 4);
        p1 = fmaf(A2.x,W2.x, fmaf(A2.y,W2.y, fmaf(A2.z,W2.z, fmaf(A2.w,W2.w, p1))));
      }
      g_logits[b*Dz + jc0 + d_i] = p0 + p1 + bcj;
    }
    grid_bar();

    // ================= phase 4: write LSTM (softmax(x) fused) =================
    {
      const float4* Lg = (const float4*)g_logits;
      const float4* Hw = (const float4*)hwp;
      float4* A4 = (float4*)sA;
      for (int idx = tid; idx < 4096; idx += 256) {
        int r = idx >> 7, c = idx & 127;
        A4[r*129 + c] = (c < 64) ? Lg[(size_t)(b0+r)*64 + c] : Hw[(size_t)(b0+r)*64 + (c-64)];
      }
      __syncthreads();
      // per-row softmax of the logits half (cols 0..255); 8 warps x 4 rows x 8 lanes
      {
        const int lane = tid & 31, w = tid >> 5;
        const int row = (w << 2) + (lane >> 3);
        const int sub = lane & 7;
        float* Arow = sA + row*SAS;
        float mx = -INFINITY;
        for (int k = sub; k < 256; k += 8) mx = fmaxf(mx, Arow[k]);
        mx = fmaxf(mx, __shfl_xor_sync(0xffffffffu, mx, 4));
        mx = fmaxf(mx, __shfl_xor_sync(0xffffffffu, mx, 2));
        mx = fmaxf(mx, __shfl_xor_sync(0xffffffffu, mx, 1));
        float sv = 0.f;
        for (int k = sub; k < 256; k += 8) { float e = expf(Arow[k]-mx); Arow[k] = e; sv += e; }
        sv += __shfl_xor_sync(0xffffffffu, sv, 4);
        sv += __shfl_xor_sync(0xffffffffu, sv, 2);
        sv += __shfl_xor_sync(0xffffffffu, sv, 1);
        float inv = 1.f / sv;
        for (int k = sub; k < 256; k += 8) Arow[k] *= inv;
      }
      __syncthreads();
      const float* Ar  = sA  + b_i*SAS;
      const float* W0p = sWw + d_i*SAS;
      const float* W1p = W0p + 8*SAS;
      const float* W2p = W0p + 16*SAS;
      const float* W3p = W0p + 24*SAS;
      float a0=0.f,a1=0.f,a2=0.f,a3=0.f;
#pragma unroll 2
      for (int k = 0; k < 512; k += 4) {
        float4 A  = *(const float4*)(Ar + k);
        float4 w0 = *(const float4*)(W0p + k);
        float4 w1 = *(const float4*)(W1p + k);
        float4 w2 = *(const float4*)(W2p + k);
        float4 w3 = *(const float4*)(W3p + k);
        a0 = fmaf(A.x,w0.x, fmaf(A.y,w0.y, fmaf(A.z,w0.z, fmaf(A.w,w0.w, a0))));
        a1 = fmaf(A.x,w1.x, fmaf(A.y,w1.y, fmaf(A.z,w1.z, fmaf(A.w,w1.w, a1))));
        a2 = fmaf(A.x,w2.x, fmaf(A.y,w2.y, fmaf(A.z,w2.z, fmaf(A.w,w2.w, a2))));
        a3 = fmaf(A.x,w3.x, fmaf(A.y,w3.y, fmaf(A.z,w3.z, fmaf(A.w,w3.w, a3))));
      }
      float ig = sigm(a0 + bw0);
      float fg = sigm(a1 + bw1);
      float gg = tanhf(a2 + bw2);
      float og = sigm(a3 + bw3);
      cw_reg = fmaf(fg, cw_reg, ig*gg);
      float hv = og * tanhf(cw_reg);
      hwc[b*Dz + d] = hv;
      out[(size_t)t*BD + b*Dz + d] = hv;
    }
    grid_bar();
  }

  // ================= final: states + M materialization =================
  {
    int i = cta*256 + tid;                  // covers BD
    out[1048576 + i]         = g_hr[BD + i];   // hr (buf 1, t=31)
    out[1048576 + 65536 + i] = g_hw[BD + i];   // hw
    out[1048576 + 32768 + b*Dz + d] = cr_reg;  // cr (thread-owned cell)
    out[1048576 + 98304 + b*Dz + d] = cw_reg;  // cw
  }
  {
    sHw[tid] = g_hw[BD + bown*Dz + tid];
    __syncthreads();
    float hwv = sHw[tid];
    float* Mo = out + 1179648 + (size_t)bown*Lz*Dz;
#pragma unroll 4
    for (int l = 0; l < Lz; l++) {
      float zv = sZ[l];
      Mo[(size_t)l*Dz + tid] = (1.f - zv) + hwv*zv;
    }
  }
}

// ---------------- launch ----------------
extern "C" void kernel_launch(void* const* d_in, const int* in_sizes, int n_in,
                              void* d_out, int out_size)
{
  const float* emb   = (const float*)d_in[0];
  const float* hr0   = (const float*)d_in[1];
  const float* cr0   = (const float*)d_in[2];
  const float* hw0   = (const float*)d_in[3];
  const float* cw0   = (const float*)d_in[4];
  const float* M     = (const float*)d_in[5];
  const int*   mask  = (const int*)d_in[6];
  const float* Wih_r = (const float*)d_in[7];
  const float* Whh_r = (const float*)d_in[8];
  const float* bih_r = (const float*)d_in[9];
  const float* bhh_r = (const float*)d_in[10];
  const float* Wc    = (const float*)d_in[11];
  const float* bc    = (const float*)d_in[12];
  const float* Wih_w = (const float*)d_in[13];
  const float* Whh_w = (const float*)d_in[14];
  const float* bih_w = (const float*)d_in[15];
  const float* bhh_w = (const float*)d_in[16];
  float* out = (float*)d_out;

  cudaFuncSetAttribute(mega, cudaFuncAttributeMaxDynamicSharedMemorySize, SMEM_BYTES);
  mega<<<NCTA, 256, SMEM_BYTES>>>(emb, hr0, cr0, hw0, cw0, M, mask,
                                  Wih_r, Whh_r, bih_r, bhh_r, Wc, bc,
                                  Wih_w, Whh_w, bih_w, bhh_w, out);
}

// round 5
// speedup vs baseline: 1.0445x; 1.0445x over previous
#include <cuda_runtime.h>
#include <math.h>

#define NCTA 128
#define NT 512
#define Bz 128
#define Lz 1024
#define Dz 256
#define Tz 32
#define BD (Bz*Dz)      /* 32768 */
#define SAS 516

// smem layout (float offsets)
#define OFF_WR 0        /* 32x516 = 16512 */
#define OFF_WW 16512    /* 16512 */
#define OFF_WC 33024    /* 8x516 = 4128 */
#define OFF_A  37152    /* 32x516 = 16512 */
#define OFF_Z  53664    /* 1024 */
#define OFF_HR 54688    /* 256 */
#define OFF_HW 54944    /* 256 */
#define OFF_RED 55200   /* 16 */
#define OFF_XC 55216    /* 512 */
#define OFF_MASK 55728  /* 256 floats = 1024 bytes */
#define SMEM_FLOATS 55984
#define SMEM_BYTES (SMEM_FLOATS*4)

// ---------------- scratch (device globals; no allocation) ----------------
__device__ float g_hr[2*BD];
__device__ float g_hw[2*BD];
__device__ float g_m[BD];
__device__ float g_logits[BD];
__device__ unsigned g_count;
__device__ unsigned g_gen;

// ---------------- helpers ----------------
__device__ __forceinline__ float warp_sum(float v){
#pragma unroll
  for (int o=16;o;o>>=1) v += __shfl_xor_sync(0xffffffffu,v,o);
  return v;
}
// 512-thread block reductions, sbuf >= 16 floats
__device__ __forceinline__ float block_sum(float v, float* sbuf){
  v = warp_sum(v);
  int lane = threadIdx.x & 31, w = threadIdx.x >> 5;
  __syncthreads();
  if (lane == 0) sbuf[w] = v;
  __syncthreads();
  float r = sbuf[0];
#pragma unroll
  for (int i=1;i<16;i++) r += sbuf[i];
  return r;
}
__device__ __forceinline__ float block_max(float v, float* sbuf){
#pragma unroll
  for (int o=16;o;o>>=1) v = fmaxf(v, __shfl_xor_sync(0xffffffffu,v,o));
  int lane = threadIdx.x & 31, w = threadIdx.x >> 5;
  __syncthreads();
  if (lane == 0) sbuf[w] = v;
  __syncthreads();
  float r = sbuf[0];
#pragma unroll
  for (int i=1;i<16;i++) r = fmaxf(r, sbuf[i]);
  return r;
}
__device__ __forceinline__ float sigm(float x){ return 1.f/(1.f+expf(-x)); }

// sense-reversing grid barrier (all 128 CTAs co-resident: 1 CTA/SM by smem)
__device__ __forceinline__ void grid_bar(){
  __threadfence();
  __syncthreads();
  if (threadIdx.x == 0) {
    unsigned gen = *(volatile unsigned*)&g_gen;
    unsigned prev = atomicAdd(&g_count, 1u);
    if (prev == NCTA - 1u) {
      atomicExch(&g_count, 0u);
      __threadfence();
      *(volatile unsigned*)&g_gen = gen + 1u;
    } else {
      while (*(volatile unsigned*)&g_gen == gen) { }
    }
    __threadfence();
  }
  __syncthreads();
}

// ---------------- the persistent mega-kernel ----------------
__global__ __launch_bounds__(NT,1) void mega(
  const float* __restrict__ emb, const float* __restrict__ hr0,
  const float* __restrict__ cr0, const float* __restrict__ hw0,
  const float* __restrict__ cw0, const float* __restrict__ M,
  const int* __restrict__ mask,
  const float* __restrict__ Wih_r, const float* __restrict__ Whh_r,
  const float* __restrict__ bih_r, const float* __restrict__ bhh_r,
  const float* __restrict__ Wc,    const float* __restrict__ bc,
  const float* __restrict__ Wih_w, const float* __restrict__ Whh_w,
  const float* __restrict__ bih_w, const float* __restrict__ bhh_w,
  float* __restrict__ out)
{
  extern __shared__ __align__(16) float sm[];
  float* sWr = sm + OFF_WR;
  float* sWw = sm + OFF_WW;
  float* sWc = sm + OFF_WC;
  float* sA  = sm + OFF_A;
  float* sZ  = sm + OFF_Z;
  float* sHr = sm + OFF_HR;
  float* sHw = sm + OFF_HW;
  float* sRed = sm + OFF_RED;
  float* sXc = sm + OFF_XC;
  unsigned char* sMask = (unsigned char*)(sm + OFF_MASK);

  const int tid = threadIdx.x;
  const int cta = blockIdx.x;
  const int jb = cta >> 2;          // 0..31
  const int bb = cta & 3;           // 0..3
  const int b0 = bb << 5;           // 32 batch rows
  const int d0 = jb << 3;           // 8 d-cols (also comp j-rows)
  const int cell = tid & 255;
  const int b_i = cell >> 3, d_i = cell & 7;
  const int gh = tid >> 8;          // gate-half: 0 -> gates i,f ; 1 -> gates g,o
  const int b = b0 + b_i, d = d0 + d_i;
  const int bown = cta;             // attention-owned batch row
  const int g0 = gh*2, g1 = gh*2 + 1;

  // ---- one-time staging: weights, mask, biases, c registers ----
  {
    const float4* Wi = (const float4*)Wih_r;
    const float4* Wh = (const float4*)Whh_r;
    float4* W4 = (float4*)sWr;
    for (int idx = tid; idx < 4096; idx += NT) {
      int r = idx >> 7, c = idx & 127;
      int j = ((r >> 3) << 8) + d0 + (r & 7);
      W4[r*129 + c] = (c < 64) ? Wi[(size_t)j*64 + c] : Wh[(size_t)j*64 + (c-64)];
    }
  }
  {
    const float4* Wi = (const float4*)Wih_w;
    const float4* Wh = (const float4*)Whh_w;
    float4* W4 = (float4*)sWw;
    for (int idx = tid; idx < 4096; idx += NT) {
      int r = idx >> 7, c = idx & 127;
      int j = ((r >> 3) << 8) + d0 + (r & 7);
      W4[r*129 + c] = (c < 64) ? Wi[(size_t)j*64 + c] : Wh[(size_t)j*64 + (c-64)];
    }
  }
  {
    const float4* Wc4 = (const float4*)Wc;
    float4* W4 = (float4*)sWc;
    for (int idx = tid; idx < 1024; idx += NT) {
      int r = idx >> 7, c = idx & 127;
      W4[r*129 + c] = Wc4[(size_t)(d0 + r)*128 + c];
    }
  }
  for (int l = tid; l < Lz; l += NT) sMask[l] = (unsigned char)(mask[bown*Lz + l] != 0);

  const float brA = bih_r[g0*256 + d] + bhh_r[g0*256 + d];
  const float brB = bih_r[g1*256 + d] + bhh_r[g1*256 + d];
  const float bwA = bih_w[g0*256 + d] + bhh_w[g0*256 + d];
  const float bwB = bih_w[g1*256 + d] + bhh_w[g1*256 + d];
  const float bcj = bc[d0 + d_i];
  float cr_reg = (gh == 0) ? cr0[b*Dz + d] : 0.f;
  float cw_reg = (gh == 0) ? cw0[b*Dz + d] : 0.f;
  __syncthreads();

  for (int t = 0; t < Tz; t++) {
    const int cur = t & 1;
    const float* hin = (t == 0) ? hr0 : g_hr + (cur^1)*BD;
    const float* hwp = (t == 0) ? hw0 : g_hw + (cur^1)*BD;
    float* hrc = g_hr + cur*BD;
    float* hwc = g_hw + cur*BD;

    // ================= phase 1: read LSTM =================
    {
      const float4* X = (const float4*)(emb + (size_t)t*BD);
      const float4* H = (const float4*)hin;
      float4* A4 = (float4*)sA;
      for (int idx = tid; idx < 4096; idx += NT) {
        int r = idx >> 7, c = idx & 127;
        A4[r*129 + c] = (c < 64) ? X[(size_t)(b0+r)*64 + c] : H[(size_t)(b0+r)*64 + (c-64)];
      }
      __syncthreads();
      const float* Ar  = sA  + b_i*SAS;
      const float* W0p = sWr + (g0*8 + d_i)*SAS;
      const float* W1p = W0p + 8*SAS;
      float x0=0.f,x1=0.f,y0=0.f,y1=0.f;
#pragma unroll 4
      for (int k = 0; k < 512; k += 8) {
        float4 A1 = *(const float4*)(Ar + k);
        float4 A2 = *(const float4*)(Ar + k + 4);
        float4 wa = *(const float4*)(W0p + k);
        float4 wb = *(const float4*)(W0p + k + 4);
        float4 wc = *(const float4*)(W1p + k);
        float4 wd = *(const float4*)(W1p + k + 4);
        x0 = fmaf(A1.x,wa.x, fmaf(A1.y,wa.y, fmaf(A1.z,wa.z, fmaf(A1.w,wa.w, x0))));
        x1 = fmaf(A2.x,wb.x, fmaf(A2.y,wb.y, fmaf(A2.z,wb.z, fmaf(A2.w,wb.w, x1))));
        y0 = fmaf(A1.x,wc.x, fmaf(A1.y,wc.y, fmaf(A1.z,wc.z, fmaf(A1.w,wc.w, y0))));
        y1 = fmaf(A2.x,wd.x, fmaf(A2.y,wd.y, fmaf(A2.z,wd.z, fmaf(A2.w,wd.w, y1))));
      }
      float accA = x0 + x1, accB = y0 + y1;
      if (gh == 1) {
        sXc[cell*2]   = tanhf(accA + brA);   // g gate
        sXc[cell*2+1] = sigm(accB + brB);    // o gate
      }
      __syncthreads();
      if (gh == 0) {
        float ig = sigm(accA + brA);
        float fg = sigm(accB + brB);
        float gg = sXc[cell*2];
        float og = sXc[cell*2+1];
        cr_reg = fmaf(fg, cr_reg, ig*gg);
        hrc[b*Dz + d] = og * tanhf(cr_reg);
      }
    }
    grid_bar();

    // ================= phase 2: attention (b = cta) =================
    if (t == 0) {
      if (tid < 256) sHr[tid] = hrc[bown*Dz + tid];
      __syncthreads();
      const int w = tid >> 5, lane = tid & 31;
      for (int l = w; l < Lz; l += 16) {
        const float* Mr = M + ((size_t)bown*Lz + l)*Dz;
        float s = 0.f;
#pragma unroll
        for (int u = 0; u < 8; u++) s = fmaf(Mr[lane + (u<<5)], sHr[lane + (u<<5)], s);
        s = warp_sum(s);
        if (lane == 0) sZ[l] = s;
      }
      __syncthreads();
      float raw[2]; float lmax = -INFINITY;
#pragma unroll
      for (int u = 0; u < 2; u++) {
        int l = tid + (u << 9);
        raw[u] = sMask[l] ? -INFINITY : sZ[l];
        lmax = fmaxf(lmax, raw[u]);
      }
      float gmax = block_max(lmax, sRed);
      float e[2]; float lsum = 0.f;
#pragma unroll
      for (int u = 0; u < 2; u++) { e[u] = expf(raw[u] - gmax); lsum += e[u]; }
      float gsum = block_sum(lsum, sRed);
      float inv = 1.f / gsum;
      __syncthreads();
#pragma unroll
      for (int u = 0; u < 2; u++) sZ[tid + (u << 9)] = e[u]*inv;
      __syncthreads();
      // m = sum_l z_l * M[b,l,:], 8-way L-split, float4 over d
      const int q = tid >> 6, dq = tid & 63;
      const float4* M4 = (const float4*)M;
      float4 acc = make_float4(0.f,0.f,0.f,0.f);
      const int lb = q << 7;
#pragma unroll 4
      for (int l = lb; l < lb + 128; l++) {
        float zv = sZ[l];
        float4 Mv = M4[((size_t)bown*Lz + l)*64 + dq];
        acc.x = fmaf(zv, Mv.x, acc.x);
        acc.y = fmaf(zv, Mv.y, acc.y);
        acc.z = fmaf(zv, Mv.z, acc.z);
        acc.w = fmaf(zv, Mv.w, acc.w);
      }
      ((float4*)sA)[q*64 + dq] = acc;
      __syncthreads();
      if (tid < 256) {
        float s = 0.f;
#pragma unroll
        for (int q2 = 0; q2 < 8; q2++) s += sA[q2*256 + tid];
        g_m[bown*Dz + tid] = s;
      }
    } else {
      if (tid < 256) { sHr[tid] = hrc[bown*Dz + tid]; sHw[tid] = hwp[bown*Dz + tid]; }
      __syncthreads();
      float hrv = (tid < 256) ? sHr[tid] : 0.f;
      float hwv = (tid < 256) ? sHw[tid] : 0.f;
      float Shr = block_sum(hrv, sRed);
      float dot = block_sum(hrv*hwv, sRed);
      float alpha = dot - Shr;
      float zp[2], raw[2]; float lmax = -INFINITY;
#pragma unroll
      for (int u = 0; u < 2; u++) {
        int l = tid + (u << 9);
        zp[u] = sZ[l];
        raw[u] = sMask[l] ? -INFINITY : fmaf(zp[u], alpha, Shr);
        lmax = fmaxf(lmax, raw[u]);
      }
      float gmax = block_max(lmax, sRed);
      float e[2]; float lsum = 0.f, lt = 0.f;
#pragma unroll
      for (int u = 0; u < 2; u++) { e[u] = expf(raw[u] - gmax); lsum += e[u]; lt += e[u]*zp[u]; }
      float gsum = block_sum(lsum, sRed);
      float gt   = block_sum(lt,   sRed);
      float inv = 1.f / gsum;
      __syncthreads();
#pragma unroll
      for (int u = 0; u < 2; u++) sZ[tid + (u << 9)] = e[u]*inv;
      float S = gt * inv;
      if (tid < 256) g_m[bown*Dz + tid] = (1.f - S) + hwv*S;
    }
    grid_bar();

    // ================= phase 3: comp logits (k-split across halves) ============
    {
      const float4* Hc = (const float4*)hrc;
      const float4* Mm = (const float4*)g_m;
      float4* A4 = (float4*)sA;
      for (int idx = tid; idx < 4096; idx += NT) {
        int r = idx >> 7, c = idx & 127;
        A4[r*129 + c] = (c < 64) ? Hc[(size_t)(b0+r)*64 + c] : Mm[(size_t)(b0+r)*64 + (c-64)];
      }
      __syncthreads();
      const float* Ar = sA  + b_i*SAS + gh*256;
      const float* Wp = sWc + d_i*SAS + gh*256;
      float p0 = 0.f, p1 = 0.f;
#pragma unroll 4
      for (int k = 0; k < 256; k += 8) {
        float4 A1 = *(const float4*)(Ar + k);
        float4 W1 = *(const float4*)(Wp + k);
        float4 A2 = *(const float4*)(Ar + k + 4);
        float4 W2 = *(const float4*)(Wp + k + 4);
        p0 = fmaf(A1.x,W1.x, fmaf(A1.y,W1.y, fmaf(A1.z,W1.z, fmaf(A1.w,W1.w, p0))));
        p1 = fmaf(A2.x,W2.x, fmaf(A2.y,W2.y, fmaf(A2.z,W2.z, fmaf(A2.w,W2.w, p1))));
      }
      float p = p0 + p1;
      if (gh == 1) sXc[cell] = p;
      __syncthreads();
      if (gh == 0) g_logits[b*Dz + d0 + d_i] = p + sXc[cell] + bcj;
    }
    grid_bar();

    // ================= phase 4: write LSTM (softmax(x) fused) =================
    {
      const float4* Lg = (const float4*)g_logits;
      const float4* Hw = (const float4*)hwp;
      float4* A4 = (float4*)sA;
      for (int idx = tid; idx < 4096; idx += NT) {
        int r = idx >> 7, c = idx & 127;
        A4[r*129 + c] = (c < 64) ? Lg[(size_t)(b0+r)*64 + c] : Hw[(size_t)(b0+r)*64 + (c-64)];
      }
      __syncthreads();
      // per-row softmax of logits half: 16 warps x 2 rows, 16 lanes per row
      {
        const int lane = tid & 31, w = tid >> 5;
        const int row = (w << 1) + (lane >> 4);
        const int sub = lane & 15;
        float* Arow = sA + row*SAS;
        float mx = -INFINITY;
        for (int k = sub; k < 256; k += 16) mx = fmaxf(mx, Arow[k]);
        mx = fmaxf(mx, __shfl_xor_sync(0xffffffffu, mx, 8));
        mx = fmaxf(mx, __shfl_xor_sync(0xffffffffu, mx, 4));
        mx = fmaxf(mx, __shfl_xor_sync(0xffffffffu, mx, 2));
        mx = fmaxf(mx, __shfl_xor_sync(0xffffffffu, mx, 1));
        float sv = 0.f;
        for (int k = sub; k < 256; k += 16) { float e = expf(Arow[k]-mx); Arow[k] = e; sv += e; }
        sv += __shfl_xor_sync(0xffffffffu, sv, 8);
        sv += __shfl_xor_sync(0xffffffffu, sv, 4);
        sv += __shfl_xor_sync(0xffffffffu, sv, 2);
        sv += __shfl_xor_sync(0xffffffffu, sv, 1);
        float inv = 1.f / sv;
        for (int k = sub; k < 256; k += 16) Arow[k] *= inv;
      }
      __syncthreads();
      const float* Ar  = sA  + b_i*SAS;
      const float* W0p = sWw + (g0*8 + d_i)*SAS;
      const float* W1p = W0p + 8*SAS;
      float x0=0.f,x1=0.f,y0=0.f,y1=0.f;
#pragma unroll 4
      for (int k = 0; k < 512; k += 8) {
        float4 A1 = *(const float4*)(Ar + k);
        float4 A2 = *(const float4*)(Ar + k + 4);
        float4 wa = *(const float4*)(W0p + k);
        float4 wb = *(const float4*)(W0p + k + 4);
        float4 wc = *(const float4*)(W1p + k);
        float4 wd = *(const float4*)(W1p + k + 4);
        x0 = fmaf(A1.x,wa.x, fmaf(A1.y,wa.y, fmaf(A1.z,wa.z, fmaf(A1.w,wa.w, x0))));
        x1 = fmaf(A2.x,wb.x, fmaf(A2.y,wb.y, fmaf(A2.z,wb.z, fmaf(A2.w,wb.w, x1))));
        y0 = fmaf(A1.x,wc.x, fmaf(A1.y,wc.y, fmaf(A1.z,wc.z, fmaf(A1.w,wc.w, y0))));
        y1 = fmaf(A2.x,wd.x, fmaf(A2.y,wd.y, fmaf(A2.z,wd.z, fmaf(A2.w,wd.w, y1))));
      }
      float accA = x0 + x1, accB = y0 + y1;
      if (gh == 1) {
        sXc[cell*2]   = tanhf(accA + bwA);
        sXc[cell*2+1] = sigm(accB + bwB);
      }
      __syncthreads();
      if (gh == 0) {
        float ig = sigm(accA + bwA);
        float fg = sigm(accB + bwB);
        float gg = sXc[cell*2];
        float og = sXc[cell*2+1];
        cw_reg = fmaf(fg, cw_reg, ig*gg);
        float hv = og * tanhf(cw_reg);
        hwc[b*Dz + d] = hv;
        out[(size_t)t*BD + b*Dz + d] = hv;
      }
    }
    grid_bar();
  }

  // ================= final: states + M materialization =================
  if (tid < 256) {
    int i = cta*256 + tid;
    out[1048576 + i]         = g_hr[BD + i];   // hr (buf 1, t=31)
    out[1048576 + 65536 + i] = g_hw[BD + i];   // hw
  }
  if (gh == 0) {
    out[1048576 + 32768 + b*Dz + d] = cr_reg;  // cr
    out[1048576 + 98304 + b*Dz + d] = cw_reg;  // cw
  }
  {
    if (tid < 256) sHw[tid] = g_hw[BD + bown*Dz + tid];
    __syncthreads();
    const int dcol = tid & 255;
    float hwv = sHw[dcol];
    float* Mo = out + 1179648 + (size_t)bown*Lz*Dz;
    const int l0 = gh << 9;
#pragma unroll 4
    for (int l = l0; l < l0 + 512; l++) {
      float zv = sZ[l];
      Mo[(size_t)l*Dz + dcol] = (1.f - zv) + hwv*zv;
    }
  }
}

// ---------------- launch ----------------
extern "C" void kernel_launch(void* const* d_in, const int* in_sizes, int n_in,
                              void* d_out, int out_size)
{
  const float* emb   = (const float*)d_in[0];
  const float* hr0   = (const float*)d_in[1];
  const float* cr0   = (const float*)d_in[2];
  const float* hw0   = (const float*)d_in[3];
  const float* cw0   = (const float*)d_in[4];
  const float* M     = (const float*)d_in[5];
  const int*   mask  = (const int*)d_in[6];
  const float* Wih_r = (const float*)d_in[7];
  const float* Whh_r = (const float*)d_in[8];
  const float* bih_r = (const float*)d_in[9];
  const float* bhh_r = (const float*)d_in[10];
  const float* Wc    = (const float*)d_in[11];
  const float* bc    = (const float*)d_in[12];
  const float* Wih_w = (const float*)d_in[13];
  const float* Whh_w = (const float*)d_in[14];
  const float* bih_w = (const float*)d_in[15];
  const float* bhh_w = (const float*)d_in[16];
  float* out = (float*)d_out;

  cudaFuncSetAttribute(mega, cudaFuncAttributeMaxDynamicSharedMemorySize, SMEM_BYTES);
  mega<<<NCTA, NT, SMEM_BYTES>>>(emb, hr0, cr0, hw0, cw0, M, mask,
                                 Wih_r, Whh_r, bih_r, bhh_r, Wc, bc,
                                 Wih_w, Whh_w, bih_w, bhh_w, out);
}

// round 6
// speedup vs baseline: 1.0976x; 1.0508x over previous
#include <cuda_runtime.h>
#include <math.h>

#define NCTA 128
#define NT 512
#define Bz 128
#define Lz 1024
#define Dz 256
#define Tz 32
#define BD (Bz*Dz)      /* 32768 */
#define SAS 516

// smem layout (float offsets)
#define OFF_WR 0        /* 32x516 = 16512 */
#define OFF_WW 16512    /* 16512 */
#define OFF_WC 33024    /* 8x516 = 4128 */
#define OFF_A  37152    /* 32x516 = 16512 */
#define OFF_Z  53664    /* 1024 */
#define OFF_HR 54688    /* 256 */
#define OFF_HW 54944    /* 256 */
#define OFF_RED 55200   /* 32 (two banks of 16) */
#define OFF_XC 55232    /* 512 */
#define OFF_MASK 55744  /* 256 floats = 1024 bytes */
#define SMEM_FLOATS 56000
#define SMEM_BYTES (SMEM_FLOATS*4)

// ---------------- scratch (device globals; no allocation) ----------------
__device__ float g_hr[2*BD];
__device__ float g_hw[2*BD];
__device__ float g_m[BD];
__device__ float g_logits[BD];
__device__ unsigned g_count;
__device__ unsigned g_gen;

// ---------------- helpers ----------------
__device__ __forceinline__ float warp_sum(float v){
#pragma unroll
  for (int o=16;o;o>>=1) v += __shfl_xor_sync(0xffffffffu,v,o);
  return v;
}
// 512-thread block reductions, sbuf >= 16 floats
__device__ __forceinline__ float block_sum(float v, float* sbuf){
  v = warp_sum(v);
  int lane = threadIdx.x & 31, w = threadIdx.x >> 5;
  __syncthreads();
  if (lane == 0) sbuf[w] = v;
  __syncthreads();
  float r = sbuf[0];
#pragma unroll
  for (int i=1;i<16;i++) r += sbuf[i];
  return r;
}
// two simultaneous sums with a single sync pair
__device__ __forceinline__ void block_sum2(float a, float b, float* sbuf,
                                           float& ra, float& rb){
  a = warp_sum(a); b = warp_sum(b);
  int lane = threadIdx.x & 31, w = threadIdx.x >> 5;
  __syncthreads();
  if (lane == 0) { sbuf[w] = a; sbuf[16 + w] = b; }
  __syncthreads();
  float xa = sbuf[0], xb = sbuf[16];
#pragma unroll
  for (int i=1;i<16;i++) { xa += sbuf[i]; xb += sbuf[16 + i]; }
  ra = xa; rb = xb;
}
__device__ __forceinline__ float block_max(float v, float* sbuf){
#pragma unroll
  for (int o=16;o;o>>=1) v = fmaxf(v, __shfl_xor_sync(0xffffffffu,v,o));
  int lane = threadIdx.x & 31, w = threadIdx.x >> 5;
  __syncthreads();
  if (lane == 0) sbuf[w] = v;
  __syncthreads();
  float r = sbuf[0];
#pragma unroll
  for (int i=1;i<16;i++) r = fmaxf(r, sbuf[i]);
  return r;
}
__device__ __forceinline__ float sigm(float x){ return 1.f/(1.f+expf(-x)); }

// grid barrier, cooperative-groups pattern: ONE thread per CTA does the
// fence + atomic + spin. Cumulative gpu-scope fences + bar.sync extend the
// release/acquire to the whole CTA; one CCTL.IVALL invalidates the SM's L1.
__device__ __forceinline__ void grid_bar(){
  __syncthreads();
  if (threadIdx.x == 0) {
    unsigned gen = *(volatile unsigned*)&g_gen;
    __threadfence();                         // release (cumulative for CTA)
    unsigned prev = atomicAdd(&g_count, 1u);
    if (prev == NCTA - 1u) {
      *(volatile unsigned*)&g_count = 0u;
      __threadfence();                       // covers reset + acts as acquire
      *(volatile unsigned*)&g_gen = gen + 1u;
    } else {
      while (*(volatile unsigned*)&g_gen == gen) { }
      __threadfence();                       // acquire + L1 invalidate
    }
  }
  __syncthreads();
}

// ---------------- the persistent mega-kernel ----------------
__global__ __launch_bounds__(NT,1) void mega(
  const float* __restrict__ emb, const float* __restrict__ hr0,
  const float* __restrict__ cr0, const float* __restrict__ hw0,
  const float* __restrict__ cw0, const float* __restrict__ M,
  const int* __restrict__ mask,
  const float* __restrict__ Wih_r, const float* __restrict__ Whh_r,
  const float* __restrict__ bih_r, const float* __restrict__ bhh_r,
  const float* __restrict__ Wc,    const float* __restrict__ bc,
  const float* __restrict__ Wih_w, const float* __restrict__ Whh_w,
  const float* __restrict__ bih_w, const float* __restrict__ bhh_w,
  float* __restrict__ out)
{
  extern __shared__ __align__(16) float sm[];
  float* sWr = sm + OFF_WR;
  float* sWw = sm + OFF_WW;
  float* sWc = sm + OFF_WC;
  float* sA  = sm + OFF_A;
  float* sZ  = sm + OFF_Z;
  float* sHr = sm + OFF_HR;
  float* sHw = sm + OFF_HW;
  float* sRed = sm + OFF_RED;
  float* sXc = sm + OFF_XC;
  unsigned char* sMask = (unsigned char*)(sm + OFF_MASK);

  const int tid = threadIdx.x;
  const int cta = blockIdx.x;
  const int jb = cta >> 2;          // 0..31
  const int bb = cta & 3;           // 0..3
  const int b0 = bb << 5;           // 32 batch rows
  const int d0 = jb << 3;           // 8 d-cols (also comp j-rows)
  const int cell = tid & 255;
  const int b_i = cell >> 3, d_i = cell & 7;
  const int gh = tid >> 8;          // gate-half: 0 -> gates i,f ; 1 -> gates g,o
  const int b = b0 + b_i, d = d0 + d_i;
  const int bown = cta;             // attention-owned batch row
  const int g0 = gh*2, g1 = gh*2 + 1;

  // ---- one-time staging: weights, mask, biases, c registers ----
  {
    const float4* Wi = (const float4*)Wih_r;
    const float4* Wh = (const float4*)Whh_r;
    float4* W4 = (float4*)sWr;
    for (int idx = tid; idx < 4096; idx += NT) {
      int r = idx >> 7, c = idx & 127;
      int j = ((r >> 3) << 8) + d0 + (r & 7);
      W4[r*129 + c] = (c < 64) ? Wi[(size_t)j*64 + c] : Wh[(size_t)j*64 + (c-64)];
    }
  }
  {
    const float4* Wi = (const float4*)Wih_w;
    const float4* Wh = (const float4*)Whh_w;
    float4* W4 = (float4*)sWw;
    for (int idx = tid; idx < 4096; idx += NT) {
      int r = idx >> 7, c = idx & 127;
      int j = ((r >> 3) << 8) + d0 + (r & 7);
      W4[r*129 + c] = (c < 64) ? Wi[(size_t)j*64 + c] : Wh[(size_t)j*64 + (c-64)];
    }
  }
  {
    const float4* Wc4 = (const float4*)Wc;
    float4* W4 = (float4*)sWc;
    for (int idx = tid; idx < 1024; idx += NT) {
      int r = idx >> 7, c = idx & 127;
      W4[r*129 + c] = Wc4[(size_t)(d0 + r)*128 + c];
    }
  }
  for (int l = tid; l < Lz; l += NT) sMask[l] = (unsigned char)(mask[bown*Lz + l] != 0);

  const float brA = bih_r[g0*256 + d] + bhh_r[g0*256 + d];
  const float brB = bih_r[g1*256 + d] + bhh_r[g1*256 + d];
  const float bwA = bih_w[g0*256 + d] + bhh_w[g0*256 + d];
  const float bwB = bih_w[g1*256 + d] + bhh_w[g1*256 + d];
  const float bcj = bc[d0 + d_i];
  float cr_reg = (gh == 0) ? cr0[b*Dz + d] : 0.f;
  float cw_reg = (gh == 0) ? cw0[b*Dz + d] : 0.f;
  __syncthreads();

  for (int t = 0; t < Tz; t++) {
    const int cur = t & 1;
    const float* hin = (t == 0) ? hr0 : g_hr + (cur^1)*BD;
    const float* hwp = (t == 0) ? hw0 : g_hw + (cur^1)*BD;
    float* hrc = g_hr + cur*BD;
    float* hwc = g_hw + cur*BD;

    // ================= phase 1: read LSTM =================
    {
      const float4* X = (const float4*)(emb + (size_t)t*BD);
      const float4* H = (const float4*)hin;
      float4* A4 = (float4*)sA;
      for (int idx = tid; idx < 4096; idx += NT) {
        int r = idx >> 7, c = idx & 127;
        A4[r*129 + c] = (c < 64) ? X[(size_t)(b0+r)*64 + c] : H[(size_t)(b0+r)*64 + (c-64)];
      }
      __syncthreads();
      const float* Ar  = sA  + b_i*SAS;
      const float* W0p = sWr + (g0*8 + d_i)*SAS;
      const float* W1p = W0p + 8*SAS;
      float x0=0.f,x1=0.f,y0=0.f,y1=0.f;
#pragma unroll 4
      for (int k = 0; k < 512; k += 8) {
        float4 A1 = *(const float4*)(Ar + k);
        float4 A2 = *(const float4*)(Ar + k + 4);
        float4 wa = *(const float4*)(W0p + k);
        float4 wb = *(const float4*)(W0p + k + 4);
        float4 wc = *(const float4*)(W1p + k);
        float4 wd = *(const float4*)(W1p + k + 4);
        x0 = fmaf(A1.x,wa.x, fmaf(A1.y,wa.y, fmaf(A1.z,wa.z, fmaf(A1.w,wa.w, x0))));
        x1 = fmaf(A2.x,wb.x, fmaf(A2.y,wb.y, fmaf(A2.z,wb.z, fmaf(A2.w,wb.w, x1))));
        y0 = fmaf(A1.x,wc.x, fmaf(A1.y,wc.y, fmaf(A1.z,wc.z, fmaf(A1.w,wc.w, y0))));
        y1 = fmaf(A2.x,wd.x, fmaf(A2.y,wd.y, fmaf(A2.z,wd.z, fmaf(A2.w,wd.w, y1))));
      }
      float accA = x0 + x1, accB = y0 + y1;
      if (gh == 1) {
        sXc[cell*2]   = tanhf(accA + brA);   // g gate
        sXc[cell*2+1] = sigm(accB + brB);    // o gate
      }
      __syncthreads();
      if (gh == 0) {
        float ig = sigm(accA + brA);
        float fg = sigm(accB + brB);
        float gg = sXc[cell*2];
        float og = sXc[cell*2+1];
        cr_reg = fmaf(fg, cr_reg, ig*gg);
        hrc[b*Dz + d] = og * tanhf(cr_reg);
      }
    }
    grid_bar();

    // ================= phase 2: attention (b = cta) =================
    if (t == 0) {
      if (tid < 256) sHr[tid] = hrc[bown*Dz + tid];
      __syncthreads();
      const int w = tid >> 5, lane = tid & 31;
      for (int l = w; l < Lz; l += 16) {
        const float* Mr = M + ((size_t)bown*Lz + l)*Dz;
        float s = 0.f;
#pragma unroll
        for (int u = 0; u < 8; u++) s = fmaf(Mr[lane + (u<<5)], sHr[lane + (u<<5)], s);
        s = warp_sum(s);
        if (lane == 0) sZ[l] = s;
      }
      __syncthreads();
      float raw[2]; float lmax = -INFINITY;
#pragma unroll
      for (int u = 0; u < 2; u++) {
        int l = tid + (u << 9);
        raw[u] = sMask[l] ? -INFINITY : sZ[l];
        lmax = fmaxf(lmax, raw[u]);
      }
      float gmax = block_max(lmax, sRed);
      float e[2]; float lsum = 0.f;
#pragma unroll
      for (int u = 0; u < 2; u++) { e[u] = expf(raw[u] - gmax); lsum += e[u]; }
      float gsum = block_sum(lsum, sRed);
      float inv = 1.f / gsum;
      __syncthreads();
#pragma unroll
      for (int u = 0; u < 2; u++) sZ[tid + (u << 9)] = e[u]*inv;
      __syncthreads();
      // m = sum_l z_l * M[b,l,:], 8-way L-split, float4 over d
      const int q = tid >> 6, dq = tid & 63;
      const float4* M4 = (const float4*)M;
      float4 acc = make_float4(0.f,0.f,0.f,0.f);
      const int lb = q << 7;
#pragma unroll 4
      for (int l = lb; l < lb + 128; l++) {
        float zv = sZ[l];
        float4 Mv = M4[((size_t)bown*Lz + l)*64 + dq];
        acc.x = fmaf(zv, Mv.x, acc.x);
        acc.y = fmaf(zv, Mv.y, acc.y);
        acc.z = fmaf(zv, Mv.z, acc.z);
        acc.w = fmaf(zv, Mv.w, acc.w);
      }
      ((float4*)sA)[q*64 + dq] = acc;
      __syncthreads();
      if (tid < 256) {
        float s = 0.f;
#pragma unroll
        for (int q2 = 0; q2 < 8; q2++) s += sA[q2*256 + tid];
        g_m[bown*Dz + tid] = s;
      }
    } else {
      if (tid < 256) { sHr[tid] = hrc[bown*Dz + tid]; sHw[tid] = hwp[bown*Dz + tid]; }
      __syncthreads();
      float hrv = (tid < 256) ? sHr[tid] : 0.f;
      float hwv = (tid < 256) ? sHw[tid] : 0.f;
      float Shr, dot;
      block_sum2(hrv, hrv*hwv, sRed, Shr, dot);
      float alpha = dot - Shr;
      float zp[2], raw[2]; float lmax = -INFINITY;
#pragma unroll
      for (int u = 0; u < 2; u++) {
        int l = tid + (u << 9);
        zp[u] = sZ[l];
        raw[u] = sMask[l] ? -INFINITY : fmaf(zp[u], alpha, Shr);
        lmax = fmaxf(lmax, raw[u]);
      }
      float gmax = block_max(lmax, sRed);
      float e[2]; float lsum = 0.f, lt = 0.f;
#pragma unroll
      for (int u = 0; u < 2; u++) { e[u] = expf(raw[u] - gmax); lsum += e[u]; lt += e[u]*zp[u]; }
      float gsum, gt;
      block_sum2(lsum, lt, sRed, gsum, gt);
      float inv = 1.f / gsum;
      __syncthreads();
#pragma unroll
      for (int u = 0; u < 2; u++) sZ[tid + (u << 9)] = e[u]*inv;
      float S = gt * inv;
      if (tid < 256) g_m[bown*Dz + tid] = (1.f - S) + hwv*S;
    }
    grid_bar();

    // ================= phase 3: comp logits (k-split across halves) ============
    {
      const float4* Hc = (const float4*)hrc;
      const float4* Mm = (const float4*)g_m;
      float4* A4 = (float4*)sA;
      for (int idx = tid; idx < 4096; idx += NT) {
        int r = idx >> 7, c = idx & 127;
        A4[r*129 + c] = (c < 64) ? Hc[(size_t)(b0+r)*64 + c] : Mm[(size_t)(b0+r)*64 + (c-64)];
      }
      __syncthreads();
      const float* Ar = sA  + b_i*SAS + gh*256;
      const float* Wp = sWc + d_i*SAS + gh*256;
      float p0 = 0.f, p1 = 0.f;
#pragma unroll 4
      for (int k = 0; k < 256; k += 8) {
        float4 A1 = *(const float4*)(Ar + k);
        float4 W1 = *(const float4*)(Wp + k);
        float4 A2 = *(const float4*)(Ar + k + 4);
        float4 W2 = *(const float4*)(Wp + k + 4);
        p0 = fmaf(A1.x,W1.x, fmaf(A1.y,W1.y, fmaf(A1.z,W1.z, fmaf(A1.w,W1.w, p0))));
        p1 = fmaf(A2.x,W2.x, fmaf(A2.y,W2.y, fmaf(A2.z,W2.z, fmaf(A2.w,W2.w, p1))));
      }
      float p = p0 + p1;
      if (gh == 1) sXc[cell] = p;
      __syncthreads();
      if (gh == 0) g_logits[b*Dz + d0 + d_i] = p + sXc[cell] + bcj;
    }
    grid_bar();

    // ================= phase 4: write LSTM (softmax(x) fused) =================
    {
      const float4* Lg = (const float4*)g_logits;
      const float4* Hw = (const float4*)hwp;
      float4* A4 = (float4*)sA;
      for (int idx = tid; idx < 4096; idx += NT) {
        int r = idx >> 7, c = idx & 127;
        A4[r*129 + c] = (c < 64) ? Lg[(size_t)(b0+r)*64 + c] : Hw[(size_t)(b0+r)*64 + (c-64)];
      }
      __syncthreads();
      // per-row softmax of logits half: 16 warps x 2 rows, 16 lanes per row
      {
        const int lane = tid & 31, w = tid >> 5;
        const int row = (w << 1) + (lane >> 4);
        const int sub = lane & 15;
        float* Arow = sA + row*SAS;
        float mx = -INFINITY;
        for (int k = sub; k < 256; k += 16) mx = fmaxf(mx, Arow[k]);
        mx = fmaxf(mx, __shfl_xor_sync(0xffffffffu, mx, 8));
        mx = fmaxf(mx, __shfl_xor_sync(0xffffffffu, mx, 4));
        mx = fmaxf(mx, __shfl_xor_sync(0xffffffffu, mx, 2));
        mx = fmaxf(mx, __shfl_xor_sync(0xffffffffu, mx, 1));
        float sv = 0.f;
        for (int k = sub; k < 256; k += 16) { float e = expf(Arow[k]-mx); Arow[k] = e; sv += e; }
        sv += __shfl_xor_sync(0xffffffffu, sv, 8);
        sv += __shfl_xor_sync(0xffffffffu, sv, 4);
        sv += __shfl_xor_sync(0xffffffffu, sv, 2);
        sv += __shfl_xor_sync(0xffffffffu, sv, 1);
        float inv = 1.f / sv;
        for (int k = sub; k < 256; k += 16) Arow[k] *= inv;
      }
      __syncthreads();
      const float* Ar  = sA  + b_i*SAS;
      const float* W0p = sWw + (g0*8 + d_i)*SAS;
      const float* W1p = W0p + 8*SAS;
      float x0=0.f,x1=0.f,y0=0.f,y1=0.f;
#pragma unroll 4
      for (int k = 0; k < 512; k += 8) {
        float4 A1 = *(const float4*)(Ar + k);
        float4 A2 = *(const float4*)(Ar + k + 4);
        float4 wa = *(const float4*)(W0p + k);
        float4 wb = *(const float4*)(W0p + k + 4);
        float4 wc = *(const float4*)(W1p + k);
        float4 wd = *(const float4*)(W1p + k + 4);
        x0 = fmaf(A1.x,wa.x, fmaf(A1.y,wa.y, fmaf(A1.z,wa.z, fmaf(A1.w,wa.w, x0))));
        x1 = fmaf(A2.x,wb.x, fmaf(A2.y,wb.y, fmaf(A2.z,wb.z, fmaf(A2.w,wb.w, x1))));
        y0 = fmaf(A1.x,wc.x, fmaf(A1.y,wc.y, fmaf(A1.z,wc.z, fmaf(A1.w,wc.w, y0))));
        y1 = fmaf(A2.x,wd.x, fmaf(A2.y,wd.y, fmaf(A2.z,wd.z, fmaf(A2.w,wd.w, y1))));
      }
      float accA = x0 + x1, accB = y0 + y1;
      if (gh == 1) {
        sXc[cell*2]   = tanhf(accA + bwA);
        sXc[cell*2+1] = sigm(accB + bwB);
      }
      __syncthreads();
      if (gh == 0) {
        float ig = sigm(accA + bwA);
        float fg = sigm(accB + bwB);
        float gg = sXc[cell*2];
        float og = sXc[cell*2+1];
        cw_reg = fmaf(fg, cw_reg, ig*gg);
        float hv = og * tanhf(cw_reg);
        hwc[b*Dz + d] = hv;
        out[(size_t)t*BD + b*Dz + d] = hv;
      }
    }
    grid_bar();
  }

  // ================= final: states + M materialization =================
  if (tid < 256) {
    int i = cta*256 + tid;
    out[1048576 + i]         = g_hr[BD + i];   // hr (buf 1, t=31)
    out[1048576 + 65536 + i] = g_hw[BD + i];   // hw
  }
  if (gh == 0) {
    out[1048576 + 32768 + b*Dz + d] = cr_reg;  // cr
    out[1048576 + 98304 + b*Dz + d] = cw_reg;  // cw
  }
  {
    if (tid < 256) sHw[tid] = g_hw[BD + bown*Dz + tid];
    __syncthreads();
    const int dcol = tid & 255;
    float hwv = sHw[dcol];
    float* Mo = out + 1179648 + (size_t)bown*Lz*Dz;
    const int l0 = gh << 9;
#pragma unroll 4
    for (int l = l0; l < l0 + 512; l++) {
      float zv = sZ[l];
      Mo[(size_t)l*Dz + dcol] = (1.f - zv) + hwv*zv;
    }
  }
}

// ---------------- launch ----------------
extern "C" void kernel_launch(void* const* d_in, const int* in_sizes, int n_in,
                              void* d_out, int out_size)
{
  const float* emb   = (const float*)d_in[0];
  const float* hr0   = (const float*)d_in[1];
  const float* cr0   = (const float*)d_in[2];
  const float* hw0   = (const float*)d_in[3];
  const float* cw0   = (const float*)d_in[4];
  const float* M     = (const float*)d_in[5];
  const int*   mask  = (const int*)d_in[6];
  const float* Wih_r = (const float*)d_in[7];
  const float* Whh_r = (const float*)d_in[8];
  const float* bih_r = (const float*)d_in[9];
  const float* bhh_r = (const float*)d_in[10];
  const float* Wc    = (const float*)d_in[11];
  const float* bc    = (const float*)d_in[12];
  const float* Wih_w = (const float*)d_in[13];
  const float* Whh_w = (const float*)d_in[14];
  const float* bih_w = (const float*)d_in[15];
  const float* bhh_w = (const float*)d_in[16];
  float* out = (float*)d_out;

  cudaFuncSetAttribute(mega, cudaFuncAttributeMaxDynamicSharedMemorySize, SMEM_BYTES);
  mega<<<NCTA, NT, SMEM_BYTES>>>(emb, hr0, cr0, hw0, cw0, M, mask,
                                 Wih_r, Whh_r, bih_r, bhh_r, Wc, bc,
                                 Wih_w, Whh_w, bih_w, bhh_w, out);
}

// round 7
// speedup vs baseline: 1.1105x; 1.0118x over previous
#include <cuda_runtime.h>
#include <math.h>

#define NCTA 128
#define NT 512
#define Bz 128
#define Lz 1024
#define Dz 256
#define Tz 32
#define BD (Bz*Dz)      /* 32768 */
#define SAS 516

// smem layout (float offsets)
#define OFF_WR 0        /* 32x516 = 16512 */
#define OFF_WW 16512    /* 16512 */
#define OFF_WC 33024    /* 8x516 = 4128 */
#define OFF_A  37152    /* 32x516 = 16512 */
#define OFF_Z  53664    /* 1024 */
#define OFF_HR 54688    /* 256 */
#define OFF_HW 54944    /* 256 */
#define OFF_RED 55200   /* 32 (two banks of 16) */
#define OFF_XC 55232    /* 512 */
#define OFF_MASK 55744  /* 256 floats = 1024 bytes */
#define SMEM_FLOATS 56000
#define SMEM_BYTES (SMEM_FLOATS*4)

// ---------------- scratch (device globals; no allocation) ----------------
__device__ float g_hr[2*BD];
__device__ float g_hw[2*BD];
__device__ float g_m[BD];
__device__ float g_logits[BD];
__device__ unsigned g_flags[NCTA*32];   // one flag per CTA, 128B padded

// ---------------- helpers ----------------
__device__ __forceinline__ float warp_sum(float v){
#pragma unroll
  for (int o=16;o;o>>=1) v += __shfl_xor_sync(0xffffffffu,v,o);
  return v;
}
// 512-thread block reductions, sbuf >= 16 floats
__device__ __forceinline__ float block_sum(float v, float* sbuf){
  v = warp_sum(v);
  int lane = threadIdx.x & 31, w = threadIdx.x >> 5;
  __syncthreads();
  if (lane == 0) sbuf[w] = v;
  __syncthreads();
  float r = sbuf[0];
#pragma unroll
  for (int i=1;i<16;i++) r += sbuf[i];
  return r;
}
// two simultaneous sums with a single sync pair
__device__ __forceinline__ void block_sum2(float a, float b, float* sbuf,
                                           float& ra, float& rb){
  a = warp_sum(a); b = warp_sum(b);
  int lane = threadIdx.x & 31, w = threadIdx.x >> 5;
  __syncthreads();
  if (lane == 0) { sbuf[w] = a; sbuf[16 + w] = b; }
  __syncthreads();
  float xa = sbuf[0], xb = sbuf[16];
#pragma unroll
  for (int i=1;i<16;i++) { xa += sbuf[i]; xb += sbuf[16 + i]; }
  ra = xa; rb = xb;
}
__device__ __forceinline__ float block_max(float v, float* sbuf){
#pragma unroll
  for (int o=16;o;o>>=1) v = fmaxf(v, __shfl_xor_sync(0xffffffffu,v,o));
  int lane = threadIdx.x & 31, w = threadIdx.x >> 5;
  __syncthreads();
  if (lane == 0) sbuf[w] = v;
  __syncthreads();
  float r = sbuf[0];
#pragma unroll
  for (int i=1;i<16;i++) r = fmaxf(r, sbuf[i]);
  return r;
}
__device__ __forceinline__ float sigm(float x){ return 1.f/(1.f+expf(-x)); }

// Contention-free grid barrier: each CTA stores its own padded flag
// (monotonic generation); threads 0..127 each poll one CTA's flag.
// No atomic RMW, no shared cache line, no master hop.
// Release/acquire: tid0 __threadfence (CCTL.IVALL) + bar.sync, as in R6.
__device__ __forceinline__ void grid_bar(unsigned gen){
  __syncthreads();
  if (threadIdx.x == 0) {
    __threadfence();                                   // release
    *(volatile unsigned*)&g_flags[blockIdx.x*32] = gen;
  }
  if (threadIdx.x < NCTA) {
    while (*(volatile unsigned*)&g_flags[threadIdx.x*32] < gen) { }
  }
  __syncthreads();
  if (threadIdx.x == 0) __threadfence();               // acquire + L1 inval
  __syncthreads();
}

// ---------------- the persistent mega-kernel ----------------
__global__ __launch_bounds__(NT,1) void mega(
  const float* __restrict__ emb, const float* __restrict__ hr0,
  const float* __restrict__ cr0, const float* __restrict__ hw0,
  const float* __restrict__ cw0, const float* __restrict__ M,
  const int* __restrict__ mask,
  const float* __restrict__ Wih_r, const float* __restrict__ Whh_r,
  const float* __restrict__ bih_r, const float* __restrict__ bhh_r,
  const float* __restrict__ Wc,    const float* __restrict__ bc,
  const float* __restrict__ Wih_w, const float* __restrict__ Whh_w,
  const float* __restrict__ bih_w, const float* __restrict__ bhh_w,
  float* __restrict__ out)
{
  extern __shared__ __align__(16) float sm[];
  float* sWr = sm + OFF_WR;
  float* sWw = sm + OFF_WW;
  float* sWc = sm + OFF_WC;
  float* sA  = sm + OFF_A;
  float* sZ  = sm + OFF_Z;
  float* sHr = sm + OFF_HR;
  float* sHw = sm + OFF_HW;
  float* sRed = sm + OFF_RED;
  float* sXc = sm + OFF_XC;
  unsigned char* sMask = (unsigned char*)(sm + OFF_MASK);

  const int tid = threadIdx.x;
  const int cta = blockIdx.x;
  const int jb = cta >> 2;          // 0..31
  const int bb = cta & 3;           // 0..3
  const int b0 = bb << 5;           // 32 batch rows
  const int d0 = jb << 3;           // 8 d-cols (also comp j-rows)
  const int cell = tid & 255;
  const int b_i = cell >> 3, d_i = cell & 7;
  const int gh = tid >> 8;          // gate-half: 0 -> gates i,f ; 1 -> gates g,o
  const int b = b0 + b_i, d = d0 + d_i;
  const int bown = cta;             // attention-owned batch row
  const int g0 = gh*2, g1 = gh*2 + 1;
  unsigned bgen = 0;

  // ---- one-time staging: weights, mask, biases, c registers ----
  {
    const float4* Wi = (const float4*)Wih_r;
    const float4* Wh = (const float4*)Whh_r;
    float4* W4 = (float4*)sWr;
    for (int idx = tid; idx < 4096; idx += NT) {
      int r = idx >> 7, c = idx & 127;
      int j = ((r >> 3) << 8) + d0 + (r & 7);
      W4[r*129 + c] = (c < 64) ? Wi[(size_t)j*64 + c] : Wh[(size_t)j*64 + (c-64)];
    }
  }
  {
    const float4* Wi = (const float4*)Wih_w;
    const float4* Wh = (const float4*)Whh_w;
    float4* W4 = (float4*)sWw;
    for (int idx = tid; idx < 4096; idx += NT) {
      int r = idx >> 7, c = idx & 127;
      int j = ((r >> 3) << 8) + d0 + (r & 7);
      W4[r*129 + c] = (c < 64) ? Wi[(size_t)j*64 + c] : Wh[(size_t)j*64 + (c-64)];
    }
  }
  {
    const float4* Wc4 = (const float4*)Wc;
    float4* W4 = (float4*)sWc;
    for (int idx = tid; idx < 1024; idx += NT) {
      int r = idx >> 7, c = idx & 127;
      W4[r*129 + c] = Wc4[(size_t)(d0 + r)*128 + c];
    }
  }
  for (int l = tid; l < Lz; l += NT) sMask[l] = (unsigned char)(mask[bown*Lz + l] != 0);

  const float brA = bih_r[g0*256 + d] + bhh_r[g0*256 + d];
  const float brB = bih_r[g1*256 + d] + bhh_r[g1*256 + d];
  const float bwA = bih_w[g0*256 + d] + bhh_w[g0*256 + d];
  const float bwB = bih_w[g1*256 + d] + bhh_w[g1*256 + d];
  const float bcj = bc[d0 + d_i];
  float cr_reg = (gh == 0) ? cr0[b*Dz + d] : 0.f;
  float cw_reg = (gh == 0) ? cw0[b*Dz + d] : 0.f;
  __syncthreads();

  for (int t = 0; t < Tz; t++) {
    const int cur = t & 1;
    const float* hin = (t == 0) ? hr0 : g_hr + (cur^1)*BD;
    const float* hwp = (t == 0) ? hw0 : g_hw + (cur^1)*BD;
    float* hrc = g_hr + cur*BD;
    float* hwc = g_hw + cur*BD;

    // ================= phase 1: read LSTM =================
    {
      const float4* X = (const float4*)(emb + (size_t)t*BD);
      const float4* H = (const float4*)hin;
      float4* A4 = (float4*)sA;
      for (int idx = tid; idx < 4096; idx += NT) {
        int r = idx >> 7, c = idx & 127;
        A4[r*129 + c] = (c < 64) ? X[(size_t)(b0+r)*64 + c] : H[(size_t)(b0+r)*64 + (c-64)];
      }
      __syncthreads();
      const float* Ar  = sA  + b_i*SAS;
      const float* W0p = sWr + (g0*8 + d_i)*SAS;
      const float* W1p = W0p + 8*SAS;
      float x0=0.f,x1=0.f,y0=0.f,y1=0.f;
#pragma unroll 4
      for (int k = 0; k < 512; k += 8) {
        float4 A1 = *(const float4*)(Ar + k);
        float4 A2 = *(const float4*)(Ar + k + 4);
        float4 wa = *(const float4*)(W0p + k);
        float4 wb = *(const float4*)(W0p + k + 4);
        float4 wc = *(const float4*)(W1p + k);
        float4 wd = *(const float4*)(W1p + k + 4);
        x0 = fmaf(A1.x,wa.x, fmaf(A1.y,wa.y, fmaf(A1.z,wa.z, fmaf(A1.w,wa.w, x0))));
        x1 = fmaf(A2.x,wb.x, fmaf(A2.y,wb.y, fmaf(A2.z,wb.z, fmaf(A2.w,wb.w, x1))));
        y0 = fmaf(A1.x,wc.x, fmaf(A1.y,wc.y, fmaf(A1.z,wc.z, fmaf(A1.w,wc.w, y0))));
        y1 = fmaf(A2.x,wd.x, fmaf(A2.y,wd.y, fmaf(A2.z,wd.z, fmaf(A2.w,wd.w, y1))));
      }
      float accA = x0 + x1, accB = y0 + y1;
      if (gh == 1) {
        sXc[cell*2]   = tanhf(accA + brA);   // g gate
        sXc[cell*2+1] = sigm(accB + brB);    // o gate
      }
      __syncthreads();
      if (gh == 0) {
        float ig = sigm(accA + brA);
        float fg = sigm(accB + brB);
        float gg = sXc[cell*2];
        float og = sXc[cell*2+1];
        cr_reg = fmaf(fg, cr_reg, ig*gg);
        hrc[b*Dz + d] = og * tanhf(cr_reg);
      }
    }
    grid_bar(++bgen);

    // ================= phase 2: attention (b = cta) =================
    if (t == 0) {
      if (tid < 256) sHr[tid] = hrc[bown*Dz + tid];
      __syncthreads();
      const int w = tid >> 5, lane = tid & 31;
      for (int l = w; l < Lz; l += 16) {
        const float* Mr = M + ((size_t)bown*Lz + l)*Dz;
        float s = 0.f;
#pragma unroll
        for (int u = 0; u < 8; u++) s = fmaf(Mr[lane + (u<<5)], sHr[lane + (u<<5)], s);
        s = warp_sum(s);
        if (lane == 0) sZ[l] = s;
      }
      __syncthreads();
      float raw[2]; float lmax = -INFINITY;
#pragma unroll
      for (int u = 0; u < 2; u++) {
        int l = tid + (u << 9);
        raw[u] = sMask[l] ? -INFINITY : sZ[l];
        lmax = fmaxf(lmax, raw[u]);
      }
      float gmax = block_max(lmax, sRed);
      float e[2]; float lsum = 0.f;
#pragma unroll
      for (int u = 0; u < 2; u++) { e[u] = expf(raw[u] - gmax); lsum += e[u]; }
      float gsum = block_sum(lsum, sRed);
      float inv = 1.f / gsum;
      __syncthreads();
#pragma unroll
      for (int u = 0; u < 2; u++) sZ[tid + (u << 9)] = e[u]*inv;
      __syncthreads();
      // m = sum_l z_l * M[b,l,:], 8-way L-split, float4 over d
      const int q = tid >> 6, dq = tid & 63;
      const float4* M4 = (const float4*)M;
      float4 acc = make_float4(0.f,0.f,0.f,0.f);
      const int lb = q << 7;
#pragma unroll 4
      for (int l = lb; l < lb + 128; l++) {
        float zv = sZ[l];
        float4 Mv = M4[((size_t)bown*Lz + l)*64 + dq];
        acc.x = fmaf(zv, Mv.x, acc.x);
        acc.y = fmaf(zv, Mv.y, acc.y);
        acc.z = fmaf(zv, Mv.z, acc.z);
        acc.w = fmaf(zv, Mv.w, acc.w);
      }
      ((float4*)sA)[q*64 + dq] = acc;
      __syncthreads();
      if (tid < 256) {
        float s = 0.f;
#pragma unroll
        for (int q2 = 0; q2 < 8; q2++) s += sA[q2*256 + tid];
        g_m[bown*Dz + tid] = s;
      }
    } else {
      if (tid < 256) { sHr[tid] = hrc[bown*Dz + tid]; sHw[tid] = hwp[bown*Dz + tid]; }
      __syncthreads();
      float hrv = (tid < 256) ? sHr[tid] : 0.f;
      float hwv = (tid < 256) ? sHw[tid] : 0.f;
      float Shr, dot;
      block_sum2(hrv, hrv*hwv, sRed, Shr, dot);
      float alpha = dot - Shr;
      float zp[2], raw[2]; float lmax = -INFINITY;
#pragma unroll
      for (int u = 0; u < 2; u++) {
        int l = tid + (u << 9);
        zp[u] = sZ[l];
        raw[u] = sMask[l] ? -INFINITY : fmaf(zp[u], alpha, Shr);
        lmax = fmaxf(lmax, raw[u]);
      }
      float gmax = block_max(lmax, sRed);
      float e[2]; float lsum = 0.f, lt = 0.f;
#pragma unroll
      for (int u = 0; u < 2; u++) { e[u] = expf(raw[u] - gmax); lsum += e[u]; lt += e[u]*zp[u]; }
      float gsum, gt;
      block_sum2(lsum, lt, sRed, gsum, gt);
      float inv = 1.f / gsum;
      __syncthreads();
#pragma unroll
      for (int u = 0; u < 2; u++) sZ[tid + (u << 9)] = e[u]*inv;
      float S = gt * inv;
      if (tid < 256) g_m[bown*Dz + tid] = (1.f - S) + hwv*S;
    }
    grid_bar(++bgen);

    // ================= phase 3: comp logits (k-split across halves) ============
    {
      const float4* Hc = (const float4*)hrc;
      const float4* Mm = (const float4*)g_m;
      float4* A4 = (float4*)sA;
      for (int idx = tid; idx < 4096; idx += NT) {
        int r = idx >> 7, c = idx & 127;
        A4[r*129 + c] = (c < 64) ? Hc[(size_t)(b0+r)*64 + c] : Mm[(size_t)(b0+r)*64 + (c-64)];
      }
      __syncthreads();
      const float* Ar = sA  + b_i*SAS + gh*256;
      const float* Wp = sWc + d_i*SAS + gh*256;
      float p0 = 0.f, p1 = 0.f;
#pragma unroll 4
      for (int k = 0; k < 256; k += 8) {
        float4 A1 = *(const float4*)(Ar + k);
        float4 W1 = *(const float4*)(Wp + k);
        float4 A2 = *(const float4*)(Ar + k + 4);
        float4 W2 = *(const float4*)(Wp + k + 4);
        p0 = fmaf(A1.x,W1.x, fmaf(A1.y,W1.y, fmaf(A1.z,W1.z, fmaf(A1.w,W1.w, p0))));
        p1 = fmaf(A2.x,W2.x, fmaf(A2.y,W2.y, fmaf(A2.z,W2.z, fmaf(A2.w,W2.w, p1))));
      }
      float p = p0 + p1;
      if (gh == 1) sXc[cell] = p;
      __syncthreads();
      if (gh == 0) g_logits[b*Dz + d0 + d_i] = p + sXc[cell] + bcj;
    }
    grid_bar(++bgen);

    // ================= phase 4: write LSTM (softmax(x) fused) =================
    {
      const float4* Lg = (const float4*)g_logits;
      const float4* Hw = (const float4*)hwp;
      float4* A4 = (float4*)sA;
      for (int idx = tid; idx < 4096; idx += NT) {
        int r = idx >> 7, c = idx & 127;
        A4[r*129 + c] = (c < 64) ? Lg[(size_t)(b0+r)*64 + c] : Hw[(size_t)(b0+r)*64 + (c-64)];
      }
      __syncthreads();
      // per-row softmax of logits half: 16 warps x 2 rows, 16 lanes per row
      {
        const int lane = tid & 31, w = tid >> 5;
        const int row = (w << 1) + (lane >> 4);
        const int sub = lane & 15;
        float* Arow = sA + row*SAS;
        float mx = -INFINITY;
        for (int k = sub; k < 256; k += 16) mx = fmaxf(mx, Arow[k]);
        mx = fmaxf(mx, __shfl_xor_sync(0xffffffffu, mx, 8));
        mx = fmaxf(mx, __shfl_xor_sync(0xffffffffu, mx, 4));
        mx = fmaxf(mx, __shfl_xor_sync(0xffffffffu, mx, 2));
        mx = fmaxf(mx, __shfl_xor_sync(0xffffffffu, mx, 1));
        float sv = 0.f;
        for (int k = sub; k < 256; k += 16) { float e = expf(Arow[k]-mx); Arow[k] = e; sv += e; }
        sv += __shfl_xor_sync(0xffffffffu, sv, 8);
        sv += __shfl_xor_sync(0xffffffffu, sv, 4);
        sv += __shfl_xor_sync(0xffffffffu, sv, 2);
        sv += __shfl_xor_sync(0xffffffffu, sv, 1);
        float inv = 1.f / sv;
        for (int k = sub; k < 256; k += 16) Arow[k] *= inv;
      }
      __syncthreads();
      const float* Ar  = sA  + b_i*SAS;
      const float* W0p = sWw + (g0*8 + d_i)*SAS;
      const float* W1p = W0p + 8*SAS;
      float x0=0.f,x1=0.f,y0=0.f,y1=0.f;
#pragma unroll 4
      for (int k = 0; k < 512; k += 8) {
        float4 A1 = *(const float4*)(Ar + k);
        float4 A2 = *(const float4*)(Ar + k + 4);
        float4 wa = *(const float4*)(W0p + k);
        float4 wb = *(const float4*)(W0p + k + 4);
        float4 wc = *(const float4*)(W1p + k);
        float4 wd = *(const float4*)(W1p + k + 4);
        x0 = fmaf(A1.x,wa.x, fmaf(A1.y,wa.y, fmaf(A1.z,wa.z, fmaf(A1.w,wa.w, x0))));
        x1 = fmaf(A2.x,wb.x, fmaf(A2.y,wb.y, fmaf(A2.z,wb.z, fmaf(A2.w,wb.w, x1))));
        y0 = fmaf(A1.x,wc.x, fmaf(A1.y,wc.y, fmaf(A1.z,wc.z, fmaf(A1.w,wc.w, y0))));
        y1 = fmaf(A2.x,wd.x, fmaf(A2.y,wd.y, fmaf(A2.z,wd.z, fmaf(A2.w,wd.w, y1))));
      }
      float accA = x0 + x1, accB = y0 + y1;
      if (gh == 1) {
        sXc[cell*2]   = tanhf(accA + bwA);
        sXc[cell*2+1] = sigm(accB + bwB);
      }
      __syncthreads();
      if (gh == 0) {
        float ig = sigm(accA + bwA);
        float fg = sigm(accB + bwB);
        float gg = sXc[cell*2];
        float og = sXc[cell*2+1];
        cw_reg = fmaf(fg, cw_reg, ig*gg);
        float hv = og * tanhf(cw_reg);
        hwc[b*Dz + d] = hv;
        out[(size_t)t*BD + b*Dz + d] = hv;
      }
    }
    grid_bar(++bgen);
  }

  // ================= final: states + M materialization =================
  if (tid < 256) {
    int i = cta*256 + tid;
    out[1048576 + i]         = g_hr[BD + i];   // hr (buf 1, t=31)
    out[1048576 + 65536 + i] = g_hw[BD + i];   // hw
  }
  if (gh == 0) {
    out[1048576 + 32768 + b*Dz + d] = cr_reg;  // cr
    out[1048576 + 98304 + b*Dz + d] = cw_reg;  // cw
  }
  {
    if (tid < 256) sHw[tid] = g_hw[BD + bown*Dz + tid];
    __syncthreads();
    const int dcol = tid & 255;
    float hwv = sHw[dcol];
    float* Mo = out + 1179648 + (size_t)bown*Lz*Dz;
    const int l0 = gh << 9;
#pragma unroll 4
    for (int l = l0; l < l0 + 512; l++) {
      float zv = sZ[l];
      Mo[(size_t)l*Dz + dcol] = (1.f - zv) + hwv*zv;
    }
  }
}

// ---------------- zero the barrier flags before each graph replay ----------
__global__ void zero_flags(){
  g_flags[threadIdx.x*32 + blockIdx.x] = 0u;   // blockIdx 0..31? launched <32,128>
}

// ---------------- launch ----------------
extern "C" void kernel_launch(void* const* d_in, const int* in_sizes, int n_in,
                              void* d_out, int out_size)
{
  const float* emb   = (const float*)d_in[0];
  const float* hr0   = (const float*)d_in[1];
  const float* cr0   = (const float*)d_in[2];
  const float* hw0   = (const float*)d_in[3];
  const float* cw0   = (const float*)d_in[4];
  const float* M     = (const float*)d_in[5];
  const int*   mask  = (const int*)d_in[6];
  const float* Wih_r = (const float*)d_in[7];
  const float* Whh_r = (const float*)d_in[8];
  const float* bih_r = (const float*)d_in[9];
  const float* bhh_r = (const float*)d_in[10];
  const float* Wc    = (const float*)d_in[11];
  const float* bc    = (const float*)d_in[12];
  const float* Wih_w = (const float*)d_in[13];
  const float* Whh_w = (const float*)d_in[14];
  const float* bih_w = (const float*)d_in[15];
  const float* bhh_w = (const float*)d_in[16];
  float* out = (float*)d_out;

  // reset flag generations so every replay starts from a known state
  zero_flags<<<32, NCTA>>>();

  cudaFuncSetAttribute(mega, cudaFuncAttributeMaxDynamicSharedMemorySize, SMEM_BYTES);
  mega<<<NCTA, NT, SMEM_BYTES>>>(emb, hr0, cr0, hw0, cw0, M, mask,
                                 Wih_r, Whh_r, bih_r, bhh_r, Wc, bc,
                                 Wih_w, Whh_w, bih_w, bhh_w, out);
}

// round 8
// speedup vs baseline: 1.6238x; 1.4622x over previous
#include <cuda_runtime.h>
#include <math.h>

#define NCTA 128
#define NT 512
#define Bz 128
#define Lz 1024
#define Dz 256
#define Tz 32
#define BD (Bz*Dz)      /* 32768 */
#define SAS 516

// smem layout (float offsets)
#define OFF_WR 0        /* 32x516 = 16512 */
#define OFF_WW 16512    /* 16512 */
#define OFF_WC 33024    /* 8x516 = 4128 */
#define OFF_A  37152    /* 32x516 = 16512 (also reused as partial buffer) */
#define OFF_Z  53664    /* 1024 */
#define OFF_HR 54688    /* 256 */
#define OFF_HW 54944    /* 256 */
#define OFF_RED 55200   /* 32 (two banks of 16) */
#define OFF_XC 55232    /* 512 */
#define OFF_MASK 55744  /* 256 floats = 1024 bytes */
#define SMEM_FLOATS 56000
#define SMEM_BYTES (SMEM_FLOATS*4)

// ---------------- scratch (device globals; no allocation) ----------------
__device__ float g_hr[2*BD];
__device__ float g_hw[2*BD];
__device__ float g_m[BD];
__device__ float g_logits[BD];
__device__ unsigned g_flags[NCTA*32];   // one flag per CTA, 128B padded

// ---------------- helpers ----------------
__device__ __forceinline__ float warp_sum(float v){
#pragma unroll
  for (int o=16;o;o>>=1) v += __shfl_xor_sync(0xffffffffu,v,o);
  return v;
}
__device__ __forceinline__ float block_sum(float v, float* sbuf){
  v = warp_sum(v);
  int lane = threadIdx.x & 31, w = threadIdx.x >> 5;
  __syncthreads();
  if (lane == 0) sbuf[w] = v;
  __syncthreads();
  float r = sbuf[0];
#pragma unroll
  for (int i=1;i<16;i++) r += sbuf[i];
  return r;
}
__device__ __forceinline__ void block_sum2(float a, float b, float* sbuf,
                                           float& ra, float& rb){
  a = warp_sum(a); b = warp_sum(b);
  int lane = threadIdx.x & 31, w = threadIdx.x >> 5;
  __syncthreads();
  if (lane == 0) { sbuf[w] = a; sbuf[16 + w] = b; }
  __syncthreads();
  float xa = sbuf[0], xb = sbuf[16];
#pragma unroll
  for (int i=1;i<16;i++) { xa += sbuf[i]; xb += sbuf[16 + i]; }
  ra = xa; rb = xb;
}
__device__ __forceinline__ float block_max(float v, float* sbuf){
#pragma unroll
  for (int o=16;o;o>>=1) v = fmaxf(v, __shfl_xor_sync(0xffffffffu,v,o));
  int lane = threadIdx.x & 31, w = threadIdx.x >> 5;
  __syncthreads();
  if (lane == 0) sbuf[w] = v;
  __syncthreads();
  float r = sbuf[0];
#pragma unroll
  for (int i=1;i<16;i++) r = fmaxf(r, sbuf[i]);
  return r;
}
__device__ __forceinline__ float sigm(float x){ return 1.f/(1.f+expf(-x)); }

// Contention-free grid barrier (R7 pattern, unchanged).
__device__ __forceinline__ void grid_bar(unsigned gen){
  __syncthreads();
  if (threadIdx.x == 0) {
    __threadfence();                                   // release
    *(volatile unsigned*)&g_flags[blockIdx.x*32] = gen;
  }
  if (threadIdx.x < NCTA) {
    while (*(volatile unsigned*)&g_flags[threadIdx.x*32] < gen) { }
  }
  __syncthreads();
  if (threadIdx.x == 0) __threadfence();               // acquire + L1 inval
  __syncthreads();
}

#define FMA4(acc, A, W) acc = fmaf((A).x,(W).x, fmaf((A).y,(W).y, fmaf((A).z,(W).z, fmaf((A).w,(W).w, (acc)))))

// GEMM 32b x 32j over K=512, k-split-4, thread tile 4b x 2j (rows jj, jj+16).
// sP may alias sA (writes happen after a syncthreads following all reads).
// Returns the two gate pre-activations for (cell, gh) via preA/preB.
__device__ __forceinline__ void gemm_phase(
    const float* sA, const float* sW, float* sP,
    int tid, int cell, int gh, float& preA, float& preB)
{
  const int kq = tid >> 7, t7 = tid & 127;
  const int jj = t7 & 15, bg = t7 >> 4;
  const int kbase = kq << 7;
  const float* A0 = sA + (bg*4+0)*SAS + kbase;
  const float* A1 = sA + (bg*4+1)*SAS + kbase;
  const float* A2 = sA + (bg*4+2)*SAS + kbase;
  const float* A3 = sA + (bg*4+3)*SAS + kbase;
  const float* W0 = sW + jj*SAS + kbase;
  const float* W1 = sW + (jj+16)*SAS + kbase;

  float a00=0.f,a01=0.f,a10=0.f,a11=0.f,a20=0.f,a21=0.f,a30=0.f,a31=0.f;
#pragma unroll 4
  for (int k = 0; k < 128; k += 8) {
    float4 w0a = *(const float4*)(W0 + k);
    float4 w0b = *(const float4*)(W0 + k + 4);
    float4 w1a = *(const float4*)(W1 + k);
    float4 w1b = *(const float4*)(W1 + k + 4);
    float4 x, y;
    x = *(const float4*)(A0 + k); y = *(const float4*)(A0 + k + 4);
    FMA4(a00,x,w0a); FMA4(a00,y,w0b); FMA4(a01,x,w1a); FMA4(a01,y,w1b);
    x = *(const float4*)(A1 + k); y = *(const float4*)(A1 + k + 4);
    FMA4(a10,x,w0a); FMA4(a10,y,w0b); FMA4(a11,x,w1a); FMA4(a11,y,w1b);
    x = *(const float4*)(A2 + k); y = *(const float4*)(A2 + k + 4);
    FMA4(a20,x,w0a); FMA4(a20,y,w0b); FMA4(a21,x,w1a); FMA4(a21,y,w1b);
    x = *(const float4*)(A3 + k); y = *(const float4*)(A3 + k + 4);
    FMA4(a30,x,w0a); FMA4(a30,y,w0b); FMA4(a31,x,w1a); FMA4(a31,y,w1b);
  }
  __syncthreads();               // all sA reads complete before overwrite
  {
    float* o = sP + kq*1064 + (bg*4)*33;
    o[0*33 + jj] = a00; o[0*33 + 16 + jj] = a01;
    o[1*33 + jj] = a10; o[1*33 + 16 + jj] = a11;
    o[2*33 + jj] = a20; o[2*33 + 16 + jj] = a21;
    o[3*33 + jj] = a30; o[3*33 + 16 + jj] = a31;
  }
  __syncthreads();
  const int b_i = cell >> 3, d_i = cell & 7;
  const int r0 = gh*16 + d_i;    // row of gate g0 = gh*2
  const int r1 = r0 + 8;         // row of gate g1
  float pa = 0.f, pb = 0.f;
#pragma unroll
  for (int q = 0; q < 4; q++) {
    pa += sP[q*1064 + b_i*33 + r0];
    pb += sP[q*1064 + b_i*33 + r1];
  }
  preA = pa; preB = pb;
}

// ---------------- the persistent mega-kernel ----------------
__global__ __launch_bounds__(NT,1) void mega(
  const float* __restrict__ emb, const float* __restrict__ hr0,
  const float* __restrict__ cr0, const float* __restrict__ hw0,
  const float* __restrict__ cw0, const float* __restrict__ M,
  const int* __restrict__ mask,
  const float* __restrict__ Wih_r, const float* __restrict__ Whh_r,
  const float* __restrict__ bih_r, const float* __restrict__ bhh_r,
  const float* __restrict__ Wc,    const float* __restrict__ bc,
  const float* __restrict__ Wih_w, const float* __restrict__ Whh_w,
  const float* __restrict__ bih_w, const float* __restrict__ bhh_w,
  float* __restrict__ out)
{
  extern __shared__ __align__(16) float sm[];
  float* sWr = sm + OFF_WR;
  float* sWw = sm + OFF_WW;
  float* sWc = sm + OFF_WC;
  float* sA  = sm + OFF_A;
  float* sZ  = sm + OFF_Z;
  float* sHr = sm + OFF_HR;
  float* sHw = sm + OFF_HW;
  float* sRed = sm + OFF_RED;
  float* sXc = sm + OFF_XC;
  unsigned char* sMask = (unsigned char*)(sm + OFF_MASK);

  const int tid = threadIdx.x;
  const int cta = blockIdx.x;
  const int jb = cta >> 2;          // 0..31
  const int bb = cta & 3;           // 0..3
  const int b0 = bb << 5;           // 32 batch rows
  const int d0 = jb << 3;           // 8 d-cols (also comp j-rows)
  const int cell = tid & 255;
  const int b_i = cell >> 3, d_i = cell & 7;
  const int gh = tid >> 8;          // gate-half: 0 -> gates i,f ; 1 -> gates g,o
  const int b = b0 + b_i, d = d0 + d_i;
  const int bown = cta;             // attention-owned batch row
  const int g0 = gh*2, g1 = gh*2 + 1;
  unsigned bgen = 0;

  // ---- one-time staging: weights (rows = g*8 + dd), mask, biases ----
  {
    const float4* Wi = (const float4*)Wih_r;
    const float4* Wh = (const float4*)Whh_r;
    float4* W4 = (float4*)sWr;
    for (int idx = tid; idx < 4096; idx += NT) {
      int r = idx >> 7, c = idx & 127;
      int j = ((r >> 3) << 8) + d0 + (r & 7);
      W4[r*129 + c] = (c < 64) ? Wi[(size_t)j*64 + c] : Wh[(size_t)j*64 + (c-64)];
    }
  }
  {
    const float4* Wi = (const float4*)Wih_w;
    const float4* Wh = (const float4*)Whh_w;
    float4* W4 = (float4*)sWw;
    for (int idx = tid; idx < 4096; idx += NT) {
      int r = idx >> 7, c = idx & 127;
      int j = ((r >> 3) << 8) + d0 + (r & 7);
      W4[r*129 + c] = (c < 64) ? Wi[(size_t)j*64 + c] : Wh[(size_t)j*64 + (c-64)];
    }
  }
  {
    const float4* Wc4 = (const float4*)Wc;
    float4* W4 = (float4*)sWc;
    for (int idx = tid; idx < 1024; idx += NT) {
      int r = idx >> 7, c = idx & 127;
      W4[r*129 + c] = Wc4[(size_t)(d0 + r)*128 + c];
    }
  }
  for (int l = tid; l < Lz; l += NT) sMask[l] = (unsigned char)(mask[bown*Lz + l] != 0);

  const float brA = bih_r[g0*256 + d] + bhh_r[g0*256 + d];
  const float brB = bih_r[g1*256 + d] + bhh_r[g1*256 + d];
  const float bwA = bih_w[g0*256 + d] + bhh_w[g0*256 + d];
  const float bwB = bih_w[g1*256 + d] + bhh_w[g1*256 + d];
  const float bcj = bc[d0 + d_i];
  float cr_reg = (gh == 0) ? cr0[b*Dz + d] : 0.f;
  float cw_reg = (gh == 0) ? cw0[b*Dz + d] : 0.f;
  __syncthreads();

  for (int t = 0; t < Tz; t++) {
    const int cur = t & 1;
    const float* hin = (t == 0) ? hr0 : g_hr + (cur^1)*BD;
    const float* hwp = (t == 0) ? hw0 : g_hw + (cur^1)*BD;
    float* hrc = g_hr + cur*BD;
    float* hwc = g_hw + cur*BD;

    // ================= phase 1: read LSTM =================
    {
      const float4* X = (const float4*)(emb + (size_t)t*BD);
      const float4* H = (const float4*)hin;
      float4* A4 = (float4*)sA;
      for (int idx = tid; idx < 4096; idx += NT) {
        int r = idx >> 7, c = idx & 127;
        A4[r*129 + c] = (c < 64) ? X[(size_t)(b0+r)*64 + c] : H[(size_t)(b0+r)*64 + (c-64)];
      }
      __syncthreads();
      float accA, accB;
      gemm_phase(sA, sWr, sA, tid, cell, gh, accA, accB);
      if (gh == 1) {
        sXc[cell*2]   = tanhf(accA + brA);   // g gate
        sXc[cell*2+1] = sigm(accB + brB);    // o gate
      }
      __syncthreads();
      if (gh == 0) {
        float ig = sigm(accA + brA);
        float fg = sigm(accB + brB);
        float gg = sXc[cell*2];
        float og = sXc[cell*2+1];
        cr_reg = fmaf(fg, cr_reg, ig*gg);
        hrc[b*Dz + d] = og * tanhf(cr_reg);
      }
    }
    grid_bar(++bgen);

    // ================= phase 2: attention (b = cta) =================
    if (t == 0) {
      if (tid < 256) sHr[tid] = hrc[bown*Dz + tid];
      __syncthreads();
      const int w = tid >> 5, lane = tid & 31;
      for (int l = w; l < Lz; l += 16) {
        const float* Mr = M + ((size_t)bown*Lz + l)*Dz;
        float s = 0.f;
#pragma unroll
        for (int u = 0; u < 8; u++) s = fmaf(Mr[lane + (u<<5)], sHr[lane + (u<<5)], s);
        s = warp_sum(s);
        if (lane == 0) sZ[l] = s;
      }
      __syncthreads();
      float raw[2]; float lmax = -INFINITY;
#pragma unroll
      for (int u = 0; u < 2; u++) {
        int l = tid + (u << 9);
        raw[u] = sMask[l] ? -INFINITY : sZ[l];
        lmax = fmaxf(lmax, raw[u]);
      }
      float gmax = block_max(lmax, sRed);
      float e[2]; float lsum = 0.f;
#pragma unroll
      for (int u = 0; u < 2; u++) { e[u] = expf(raw[u] - gmax); lsum += e[u]; }
      float gsum = block_sum(lsum, sRed);
      float inv = 1.f / gsum;
      __syncthreads();
#pragma unroll
      for (int u = 0; u < 2; u++) sZ[tid + (u << 9)] = e[u]*inv;
      __syncthreads();
      // m = sum_l z_l * M[b,l,:], 8-way L-split, float4 over d
      const int q = tid >> 6, dq = tid & 63;
      const float4* M4 = (const float4*)M;
      float4 acc = make_float4(0.f,0.f,0.f,0.f);
      const int lb = q << 7;
#pragma unroll 4
      for (int l = lb; l < lb + 128; l++) {
        float zv = sZ[l];
        float4 Mv = M4[((size_t)bown*Lz + l)*64 + dq];
        acc.x = fmaf(zv, Mv.x, acc.x);
        acc.y = fmaf(zv, Mv.y, acc.y);
        acc.z = fmaf(zv, Mv.z, acc.z);
        acc.w = fmaf(zv, Mv.w, acc.w);
      }
      ((float4*)sA)[q*64 + dq] = acc;
      __syncthreads();
      if (tid < 256) {
        float s = 0.f;
#pragma unroll
        for (int q2 = 0; q2 < 8; q2++) s += sA[q2*256 + tid];
        g_m[bown*Dz + tid] = s;
      }
    } else {
      if (tid < 256) { sHr[tid] = hrc[bown*Dz + tid]; sHw[tid] = hwp[bown*Dz + tid]; }
      __syncthreads();
      float hrv = (tid < 256) ? sHr[tid] : 0.f;
      float hwv = (tid < 256) ? sHw[tid] : 0.f;
      float Shr, dot;
      block_sum2(hrv, hrv*hwv, sRed, Shr, dot);
      float alpha = dot - Shr;
      float zp[2], raw[2]; float lmax = -INFINITY;
#pragma unroll
      for (int u = 0; u < 2; u++) {
        int l = tid + (u << 9);
        zp[u] = sZ[l];
        raw[u] = sMask[l] ? -INFINITY : fmaf(zp[u], alpha, Shr);
        lmax = fmaxf(lmax, raw[u]);
      }
      float gmax = block_max(lmax, sRed);
      float e[2]; float lsum = 0.f, lt = 0.f;
#pragma unroll
      for (int u = 0; u < 2; u++) { e[u] = expf(raw[u] - gmax); lsum += e[u]; lt += e[u]*zp[u]; }
      float gsum, gt;
      block_sum2(lsum, lt, sRed, gsum, gt);
      float inv = 1.f / gsum;
      __syncthreads();
#pragma unroll
      for (int u = 0; u < 2; u++) sZ[tid + (u << 9)] = e[u]*inv;
      float S = gt * inv;
      if (tid < 256) g_m[bown*Dz + tid] = (1.f - S) + hwv*S;
    }
    grid_bar(++bgen);

    // ================= phase 3: comp logits (k-split across halves) ============
    {
      const float4* Hc = (const float4*)hrc;
      const float4* Mm = (const float4*)g_m;
      float4* A4 = (float4*)sA;
      for (int idx = tid; idx < 4096; idx += NT) {
        int r = idx >> 7, c = idx & 127;
        A4[r*129 + c] = (c < 64) ? Hc[(size_t)(b0+r)*64 + c] : Mm[(size_t)(b0+r)*64 + (c-64)];
      }
      __syncthreads();
      const float* Ar = sA  + b_i*SAS + gh*256;
      const float* Wp = sWc + d_i*SAS + gh*256;
      float p0 = 0.f, p1 = 0.f;
#pragma unroll 4
      for (int k = 0; k < 256; k += 8) {
        float4 A1 = *(const float4*)(Ar + k);
        float4 W1 = *(const float4*)(Wp + k);
        float4 A2 = *(const float4*)(Ar + k + 4);
        float4 W2 = *(const float4*)(Wp + k + 4);
        FMA4(p0, A1, W1);
        FMA4(p1, A2, W2);
      }
      float p = p0 + p1;
      if (gh == 1) sXc[cell] = p;
      __syncthreads();
      if (gh == 0) g_logits[b*Dz + d0 + d_i] = p + sXc[cell] + bcj;
    }
    grid_bar(++bgen);

    // ================= phase 4: write LSTM (softmax(x) fused) =================
    {
      const float4* Lg = (const float4*)g_logits;
      const float4* Hw = (const float4*)hwp;
      float4* A4 = (float4*)sA;
      for (int idx = tid; idx < 4096; idx += NT) {
        int r = idx >> 7, c = idx & 127;
        A4[r*129 + c] = (c < 64) ? Lg[(size_t)(b0+r)*64 + c] : Hw[(size_t)(b0+r)*64 + (c-64)];
      }
      __syncthreads();
      // per-row softmax of logits half: 16 warps x 2 rows, 16 lanes per row
      {
        const int lane = tid & 31, w = tid >> 5;
        const int row = (w << 1) + (lane >> 4);
        const int sub = lane & 15;
        float* Arow = sA + row*SAS;
        float mx = -INFINITY;
        for (int k = sub; k < 256; k += 16) mx = fmaxf(mx, Arow[k]);
        mx = fmaxf(mx, __shfl_xor_sync(0xffffffffu, mx, 8));
        mx = fmaxf(mx, __shfl_xor_sync(0xffffffffu, mx, 4));
        mx = fmaxf(mx, __shfl_xor_sync(0xffffffffu, mx, 2));
        mx = fmaxf(mx, __shfl_xor_sync(0xffffffffu, mx, 1));
        float sv = 0.f;
        for (int k = sub; k < 256; k += 16) { float e = expf(Arow[k]-mx); Arow[k] = e; sv += e; }
        sv += __shfl_xor_sync(0xffffffffu, sv, 8);
        sv += __shfl_xor_sync(0xffffffffu, sv, 4);
        sv += __shfl_xor_sync(0xffffffffu, sv, 2);
        sv += __shfl_xor_sync(0xffffffffu, sv, 1);
        float inv = 1.f / sv;
        for (int k = sub; k < 256; k += 16) Arow[k] *= inv;
      }
      __syncthreads();
      float accA, accB;
      gemm_phase(sA, sWw, sA, tid, cell, gh, accA, accB);
      if (gh == 1) {
        sXc[cell*2]   = tanhf(accA + bwA);
        sXc[cell*2+1] = sigm(accB + bwB);
      }
      __syncthreads();
      if (gh == 0) {
        float ig = sigm(accA + bwA);
        float fg = sigm(accB + bwB);
        float gg = sXc[cell*2];
        float og = sXc[cell*2+1];
        cw_reg = fmaf(fg, cw_reg, ig*gg);
        float hv = og * tanhf(cw_reg);
        hwc[b*Dz + d] = hv;
        out[(size_t)t*BD + b*Dz + d] = hv;
      }
    }
    // NO grid barrier here: hw/out written in phase 4 are first consumed
    // cross-CTA only after the next step's phase-1 barrier.
  }
  grid_bar(++bgen);   // make final-step hw/hr visible for the epilogue

  // ================= final: states + M materialization =================
  if (tid < 256) {
    int i = cta*256 + tid;
    out[1048576 + i]         = g_hr[BD + i];   // hr (buf 1, t=31)
    out[1048576 + 65536 + i] = g_hw[BD + i];   // hw
  }
  if (gh == 0) {
    out[1048576 + 32768 + b*Dz + d] = cr_reg;  // cr
    out[1048576 + 98304 + b*Dz + d] = cw_reg;  // cw
  }
  {
    if (tid < 256) sHw[tid] = g_hw[BD + bown*Dz + tid];
    __syncthreads();
    const int dcol = tid & 255;
    float hwv = sHw[dcol];
    float* Mo = out + 1179648 + (size_t)bown*Lz*Dz;
    const int l0 = gh << 9;
#pragma unroll 4
    for (int l = l0; l < l0 + 512; l++) {
      float zv = sZ[l];
      Mo[(size_t)l*Dz + dcol] = (1.f - zv) + hwv*zv;
    }
  }
}

// ---------------- zero the barrier flags before each graph replay ----------
__global__ void zero_flags(){
  g_flags[threadIdx.x*32 + blockIdx.x] = 0u;
}

// ---------------- launch ----------------
extern "C" void kernel_launch(void* const* d_in, const int* in_sizes, int n_in,
                              void* d_out, int out_size)
{
  const float* emb   = (const float*)d_in[0];
  const float* hr0   = (const float*)d_in[1];
  const float* cr0   = (const float*)d_in[2];
  const float* hw0   = (const float*)d_in[3];
  const float* cw0   = (const float*)d_in[4];
  const float* M     = (const float*)d_in[5];
  const int*   mask  = (const int*)d_in[6];
  const float* Wih_r = (const float*)d_in[7];
  const float* Whh_r = (const float*)d_in[8];
  const float* bih_r = (const float*)d_in[9];
  const float* bhh_r = (const float*)d_in[10];
  const float* Wc    = (const float*)d_in[11];
  const float* bc    = (const float*)d_in[12];
  const float* Wih_w = (const float*)d_in[13];
  const float* Whh_w = (const float*)d_in[14];
  const float* bih_w = (const float*)d_in[15];
  const float* bhh_w = (const float*)d_in[16];
  float* out = (float*)d_out;

  zero_flags<<<32, NCTA>>>();

  cudaFuncSetAttribute(mega, cudaFuncAttributeMaxDynamicSharedMemorySize, SMEM_BYTES);
  mega<<<NCTA, NT, SMEM_BYTES>>>(emb, hr0, cr0, hw0, cw0, M, mask,
                                 Wih_r, Whh_r, bih_r, bhh_r, Wc, bc,
                                 Wih_w, Whh_w, bih_w, bhh_w, out);
}

// round 9
// speedup vs baseline: 2.0764x; 1.2787x over previous
#include <cuda_runtime.h>
#include <math.h>

#define NCTA 128
#define NT 512
#define Bz 128
#define Lz 1024
#define Dz 256
#define Tz 32
#define BD (Bz*Dz)      /* 32768 */
#define SAS 516

// smem layout (float offsets)
#define OFF_WR 0        /* 32x516 = 16512 */
#define OFF_WW 16512    /* 16512 */
#define OFF_WC 33024    /* 8x516 = 4128 */
#define OFF_A  37152    /* 32x516 = 16512 (also reused as partial buffer) */
#define OFF_Z  53664    /* 1024 */
#define OFF_HR 54688    /* 256 */
#define OFF_HW 54944    /* 256 */
#define OFF_RED 55200   /* 32 (two banks of 16) */
#define OFF_XC 55232    /* 512 */
#define OFF_MASK 55744  /* 256 floats = 1024 bytes */
#define SMEM_FLOATS 56000
#define SMEM_BYTES (SMEM_FLOATS*4)

// ---------------- scratch (device globals; no allocation) ----------------
__device__ float g_hr[2*BD];
__device__ float g_hw[2*BD];
__device__ float g_m[BD];
__device__ float g_logits[BD];
__device__ unsigned g_flags[NCTA*32];   // one flag per CTA, 128B padded

// ---------------- helpers ----------------
__device__ __forceinline__ float warp_sum(float v){
#pragma unroll
  for (int o=16;o;o>>=1) v += __shfl_xor_sync(0xffffffffu,v,o);
  return v;
}
__device__ __forceinline__ float block_sum(float v, float* sbuf){
  v = warp_sum(v);
  int lane = threadIdx.x & 31, w = threadIdx.x >> 5;
  __syncthreads();
  if (lane == 0) sbuf[w] = v;
  __syncthreads();
  float r = sbuf[0];
#pragma unroll
  for (int i=1;i<16;i++) r += sbuf[i];
  return r;
}
__device__ __forceinline__ void block_sum2(float a, float b, float* sbuf,
                                           float& ra, float& rb){
  a = warp_sum(a); b = warp_sum(b);
  int lane = threadIdx.x & 31, w = threadIdx.x >> 5;
  __syncthreads();
  if (lane == 0) { sbuf[w] = a; sbuf[16 + w] = b; }
  __syncthreads();
  float xa = sbuf[0], xb = sbuf[16];
#pragma unroll
  for (int i=1;i<16;i++) { xa += sbuf[i]; xb += sbuf[16 + i]; }
  ra = xa; rb = xb;
}
__device__ __forceinline__ float block_max(float v, float* sbuf){
#pragma unroll
  for (int o=16;o;o>>=1) v = fmaxf(v, __shfl_xor_sync(0xffffffffu,v,o));
  int lane = threadIdx.x & 31, w = threadIdx.x >> 5;
  __syncthreads();
  if (lane == 0) sbuf[w] = v;
  __syncthreads();
  float r = sbuf[0];
#pragma unroll
  for (int i=1;i<16;i++) r = fmaxf(r, sbuf[i]);
  return r;
}
__device__ __forceinline__ float sigm(float x){ return 1.f/(1.f+expf(-x)); }

// round fp32 -> tf32 (round-to-nearest), kept in a float register
__device__ __forceinline__ float tf32r(float x){
  unsigned u;
  asm("cvt.rna.tf32.f32 %0, %1;" : "=r"(u) : "f"(x));
  return __uint_as_float(u);
}
__device__ __forceinline__ float4 tf32r4(float4 v){
  v.x = tf32r(v.x); v.y = tf32r(v.y); v.z = tf32r(v.z); v.w = tf32r(v.w);
  return v;
}

// Contention-free grid barrier (R7 pattern, unchanged).
__device__ __forceinline__ void grid_bar(unsigned gen){
  __syncthreads();
  if (threadIdx.x == 0) {
    __threadfence();                                   // release
    *(volatile unsigned*)&g_flags[blockIdx.x*32] = gen;
  }
  if (threadIdx.x < NCTA) {
    while (*(volatile unsigned*)&g_flags[threadIdx.x*32] < gen) { }
  }
  __syncthreads();
  if (threadIdx.x == 0) __threadfence();               // acquire + L1 inval
  __syncthreads();
}

#define MMA_TF32(c0,c1,c2,c3,a0,a1,a2,a3,b0,b1) \
  asm volatile("mma.sync.aligned.m16n8k8.row.col.f32.tf32.tf32.f32 " \
    "{%0,%1,%2,%3}, {%4,%5,%6,%7}, {%8,%9}, {%0,%1,%2,%3};" \
    : "+f"(c0),"+f"(c1),"+f"(c2),"+f"(c3) \
    : "r"(a0),"r"(a1),"r"(a2),"r"(a3),"r"(b0),"r"(b1))

// LSTM GEMM via tf32 mma: C[32b x 32j] = A[32 x 512] * W[32 x 512]^T.
// 16 warps = mt(2 m16) x ntt(2 n16) x kh(4 k128). sA/sW hold tf32-rounded fp32.
// sP may alias sA (all reads complete before the internal sync).
__device__ __forceinline__ void gemm_lstm(
    const float* sA, const float* sW, float* sP,
    int tid, int cell, int gh, float& preA, float& preB)
{
  const int lane = tid & 31, w = tid >> 5;
  const int kh = w & 3, mt = (w >> 2) & 1, ntt = w >> 3;
  const int gid = lane >> 2, tig = lane & 3;
  const int m0 = mt << 4, n0 = ntt << 4;
  const int kb = kh << 7;
  const float* A0 = sA + (m0 + gid)*SAS + kb + tig;
  const float* A1 = A0 + 8*SAS;
  const float* B0 = sW + (n0 + gid)*SAS + kb + tig;
  const float* B1 = B0 + 8*SAS;

  float c00=0.f,c01=0.f,c02=0.f,c03=0.f;
  float c10=0.f,c11=0.f,c12=0.f,c13=0.f;
#pragma unroll
  for (int i = 0; i < 16; i++) {
    const int k = i << 3;
    unsigned a0 = __float_as_uint(A0[k]);
    unsigned a1 = __float_as_uint(A1[k]);
    unsigned a2 = __float_as_uint(A0[k+4]);
    unsigned a3 = __float_as_uint(A1[k+4]);
    unsigned b0 = __float_as_uint(B0[k]);
    unsigned b1 = __float_as_uint(B0[k+4]);
    unsigned b2 = __float_as_uint(B1[k]);
    unsigned b3 = __float_as_uint(B1[k+4]);
    MMA_TF32(c00,c01,c02,c03, a0,a1,a2,a3, b0,b1);
    MMA_TF32(c10,c11,c12,c13, a0,a1,a2,a3, b2,b3);
  }
  __syncthreads();               // all sA reads complete before overwrite
  {
    float* r0p = sP + ((kh<<5) + m0 + gid)*33 + n0 + (tig<<1);
    float* r1p = r0p + 8*33;
    r0p[0] = c00; r0p[1] = c01;
    r1p[0] = c02; r1p[1] = c03;
    r0p[8] = c10; r0p[9] = c11;
    r1p[8] = c12; r1p[9] = c13;
  }
  __syncthreads();
  const int b_i = cell >> 3, d_i = cell & 7;
  const int r0 = (gh<<4) + d_i;      // gate g0 column
  const int r1 = r0 + 8;             // gate g1 column
  float pa = 0.f, pb = 0.f;
#pragma unroll
  for (int q = 0; q < 4; q++) {
    const float* row = sP + ((q<<5) + b_i)*33;
    pa += row[r0];
    pb += row[r1];
  }
  preA = pa; preB = pb;
}

// ---------------- the persistent mega-kernel ----------------
__global__ __launch_bounds__(NT,1) void mega(
  const float* __restrict__ emb, const float* __restrict__ hr0,
  const float* __restrict__ cr0, const float* __restrict__ hw0,
  const float* __restrict__ cw0, const float* __restrict__ M,
  const int* __restrict__ mask,
  const float* __restrict__ Wih_r, const float* __restrict__ Whh_r,
  const float* __restrict__ bih_r, const float* __restrict__ bhh_r,
  const float* __restrict__ Wc,    const float* __restrict__ bc,
  const float* __restrict__ Wih_w, const float* __restrict__ Whh_w,
  const float* __restrict__ bih_w, const float* __restrict__ bhh_w,
  float* __restrict__ out)
{
  extern __shared__ __align__(16) float sm[];
  float* sWr = sm + OFF_WR;
  float* sWw = sm + OFF_WW;
  float* sWc = sm + OFF_WC;
  float* sA  = sm + OFF_A;
  float* sZ  = sm + OFF_Z;
  float* sHr = sm + OFF_HR;
  float* sHw = sm + OFF_HW;
  float* sRed = sm + OFF_RED;
  float* sXc = sm + OFF_XC;
  unsigned char* sMask = (unsigned char*)(sm + OFF_MASK);

  const int tid = threadIdx.x;
  const int cta = blockIdx.x;
  const int jb = cta >> 2;          // 0..31
  const int bb = cta & 3;           // 0..3
  const int b0 = bb << 5;           // 32 batch rows
  const int d0 = jb << 3;           // 8 d-cols (also comp j-rows)
  const int cell = tid & 255;
  const int b_i = cell >> 3, d_i = cell & 7;
  const int gh = tid >> 8;          // gate-half: 0 -> gates i,f ; 1 -> gates g,o
  const int b = b0 + b_i, d = d0 + d_i;
  const int bown = cta;             // attention-owned batch row
  const int g0 = gh*2, g1 = gh*2 + 1;
  unsigned bgen = 0;

  // ---- one-time staging: weights (tf32-rounded), mask, biases ----
  {
    const float4* Wi = (const float4*)Wih_r;
    const float4* Wh = (const float4*)Whh_r;
    float4* W4 = (float4*)sWr;
    for (int idx = tid; idx < 4096; idx += NT) {
      int r = idx >> 7, c = idx & 127;
      int j = ((r >> 3) << 8) + d0 + (r & 7);
      float4 v = (c < 64) ? Wi[(size_t)j*64 + c] : Wh[(size_t)j*64 + (c-64)];
      W4[r*129 + c] = tf32r4(v);
    }
  }
  {
    const float4* Wi = (const float4*)Wih_w;
    const float4* Wh = (const float4*)Whh_w;
    float4* W4 = (float4*)sWw;
    for (int idx = tid; idx < 4096; idx += NT) {
      int r = idx >> 7, c = idx & 127;
      int j = ((r >> 3) << 8) + d0 + (r & 7);
      float4 v = (c < 64) ? Wi[(size_t)j*64 + c] : Wh[(size_t)j*64 + (c-64)];
      W4[r*129 + c] = tf32r4(v);
    }
  }
  {
    const float4* Wc4 = (const float4*)Wc;
    float4* W4 = (float4*)sWc;
    for (int idx = tid; idx < 1024; idx += NT) {
      int r = idx >> 7, c = idx & 127;
      W4[r*129 + c] = tf32r4(Wc4[(size_t)(d0 + r)*128 + c]);
    }
  }
  for (int l = tid; l < Lz; l += NT) sMask[l] = (unsigned char)(mask[bown*Lz + l] != 0);

  const float brA = bih_r[g0*256 + d] + bhh_r[g0*256 + d];
  const float brB = bih_r[g1*256 + d] + bhh_r[g1*256 + d];
  const float bwA = bih_w[g0*256 + d] + bhh_w[g0*256 + d];
  const float bwB = bih_w[g1*256 + d] + bhh_w[g1*256 + d];
  const float bcj = bc[d0 + d_i];
  float cr_reg = (gh == 0) ? cr0[b*Dz + d] : 0.f;
  float cw_reg = (gh == 0) ? cw0[b*Dz + d] : 0.f;
  __syncthreads();

  for (int t = 0; t < Tz; t++) {
    const int cur = t & 1;
    const float* hin = (t == 0) ? hr0 : g_hr + (cur^1)*BD;
    const float* hwp = (t == 0) ? hw0 : g_hw + (cur^1)*BD;
    float* hrc = g_hr + cur*BD;
    float* hwc = g_hw + cur*BD;

    // ================= phase 1: read LSTM =================
    {
      const float4* X = (const float4*)(emb + (size_t)t*BD);
      const float4* H = (const float4*)hin;
      float4* A4 = (float4*)sA;
      for (int idx = tid; idx < 4096; idx += NT) {
        int r = idx >> 7, c = idx & 127;
        float4 v = (c < 64) ? X[(size_t)(b0+r)*64 + c] : H[(size_t)(b0+r)*64 + (c-64)];
        A4[r*129 + c] = tf32r4(v);
      }
      __syncthreads();
      float accA, accB;
      gemm_lstm(sA, sWr, sA, tid, cell, gh, accA, accB);
      if (gh == 1) {
        sXc[cell*2]   = tanhf(accA + brA);   // g gate
        sXc[cell*2+1] = sigm(accB + brB);    // o gate
      }
      __syncthreads();
      if (gh == 0) {
        float ig = sigm(accA + brA);
        float fg = sigm(accB + brB);
        float gg = sXc[cell*2];
        float og = sXc[cell*2+1];
        cr_reg = fmaf(fg, cr_reg, ig*gg);
        hrc[b*Dz + d] = og * tanhf(cr_reg);
      }
    }
    grid_bar(++bgen);

    // ================= phase 2: attention (b = cta) =================
    if (t == 0) {
      if (tid < 256) sHr[tid] = hrc[bown*Dz + tid];
      __syncthreads();
      const int w = tid >> 5, lane = tid & 31;
      for (int l = w; l < Lz; l += 16) {
        const float* Mr = M + ((size_t)bown*Lz + l)*Dz;
        float s = 0.f;
#pragma unroll
        for (int u = 0; u < 8; u++) s = fmaf(Mr[lane + (u<<5)], sHr[lane + (u<<5)], s);
        s = warp_sum(s);
        if (lane == 0) sZ[l] = s;
      }
      __syncthreads();
      float raw[2]; float lmax = -INFINITY;
#pragma unroll
      for (int u = 0; u < 2; u++) {
        int l = tid + (u << 9);
        raw[u] = sMask[l] ? -INFINITY : sZ[l];
        lmax = fmaxf(lmax, raw[u]);
      }
      float gmax = block_max(lmax, sRed);
      float e[2]; float lsum = 0.f;
#pragma unroll
      for (int u = 0; u < 2; u++) { e[u] = expf(raw[u] - gmax); lsum += e[u]; }
      float gsum = block_sum(lsum, sRed);
      float inv = 1.f / gsum;
      __syncthreads();
#pragma unroll
      for (int u = 0; u < 2; u++) sZ[tid + (u << 9)] = e[u]*inv;
      __syncthreads();
      // m = sum_l z_l * M[b,l,:], 8-way L-split, float4 over d
      const int q = tid >> 6, dq = tid & 63;
      const float4* M4 = (const float4*)M;
      float4 acc = make_float4(0.f,0.f,0.f,0.f);
      const int lb = q << 7;
#pragma unroll 4
      for (int l = lb; l < lb + 128; l++) {
        float zv = sZ[l];
        float4 Mv = M4[((size_t)bown*Lz + l)*64 + dq];
        acc.x = fmaf(zv, Mv.x, acc.x);
        acc.y = fmaf(zv, Mv.y, acc.y);
        acc.z = fmaf(zv, Mv.z, acc.z);
        acc.w = fmaf(zv, Mv.w, acc.w);
      }
      ((float4*)sA)[q*64 + dq] = acc;
      __syncthreads();
      if (tid < 256) {
        float s = 0.f;
#pragma unroll
        for (int q2 = 0; q2 < 8; q2++) s += sA[q2*256 + tid];
        g_m[bown*Dz + tid] = s;
      }
    } else {
      if (tid < 256) { sHr[tid] = hrc[bown*Dz + tid]; sHw[tid] = hwp[bown*Dz + tid]; }
      __syncthreads();
      float hrv = (tid < 256) ? sHr[tid] : 0.f;
      float hwv = (tid < 256) ? sHw[tid] : 0.f;
      float Shr, dot;
      block_sum2(hrv, hrv*hwv, sRed, Shr, dot);
      float alpha = dot - Shr;
      float zp[2], raw[2]; float lmax = -INFINITY;
#pragma unroll
      for (int u = 0; u < 2; u++) {
        int l = tid + (u << 9);
        zp[u] = sZ[l];
        raw[u] = sMask[l] ? -INFINITY : fmaf(zp[u], alpha, Shr);
        lmax = fmaxf(lmax, raw[u]);
      }
      float gmax = block_max(lmax, sRed);
      float e[2]; float lsum = 0.f, lt = 0.f;
#pragma unroll
      for (int u = 0; u < 2; u++) { e[u] = expf(raw[u] - gmax); lsum += e[u]; lt += e[u]*zp[u]; }
      float gsum, gt;
      block_sum2(lsum, lt, sRed, gsum, gt);
      float inv = 1.f / gsum;
      __syncthreads();
#pragma unroll
      for (int u = 0; u < 2; u++) sZ[tid + (u << 9)] = e[u]*inv;
      float S = gt * inv;
      if (tid < 256) g_m[bown*Dz + tid] = (1.f - S) + hwv*S;
    }
    grid_bar(++bgen);

    // ================= phase 3: comp logits (tf32 mma) =================
    {
      const float4* Hc = (const float4*)hrc;
      const float4* Mm = (const float4*)g_m;
      float4* A4 = (float4*)sA;
      for (int idx = tid; idx < 4096; idx += NT) {
        int r = idx >> 7, c = idx & 127;
        float4 v = (c < 64) ? Hc[(size_t)(b0+r)*64 + c] : Mm[(size_t)(b0+r)*64 + (c-64)];
        A4[r*129 + c] = tf32r4(v);
      }
      __syncthreads();
      // 16 warps = mt(2) x kh(8 of k64). C[32 x 8] = A * Wc^T
      {
        const int lane = tid & 31, w = tid >> 5;
        const int mt = w & 1, kh = w >> 1;
        const int gid = lane >> 2, tig = lane & 3;
        const int m0 = mt << 4;
        const int kb = kh << 6;
        const float* A0 = sA + (m0 + gid)*SAS + kb + tig;
        const float* A1 = A0 + 8*SAS;
        const float* B0 = sWc + gid*SAS + kb + tig;
        float c0=0.f,c1=0.f,c2=0.f,c3=0.f;
#pragma unroll
        for (int i = 0; i < 8; i++) {
          const int k = i << 3;
          unsigned a0 = __float_as_uint(A0[k]);
          unsigned a1 = __float_as_uint(A1[k]);
          unsigned a2 = __float_as_uint(A0[k+4]);
          unsigned a3 = __float_as_uint(A1[k+4]);
          unsigned b0r = __float_as_uint(B0[k]);
          unsigned b1r = __float_as_uint(B0[k+4]);
          MMA_TF32(c0,c1,c2,c3, a0,a1,a2,a3, b0r,b1r);
        }
        __syncthreads();        // sA reads done before partial overwrite
        float* r0p = sA + ((kh<<5) + m0 + gid)*9 + (tig<<1);
        float* r1p = r0p + 8*9;
        r0p[0] = c0; r0p[1] = c1;
        r1p[0] = c2; r1p[1] = c3;
      }
      __syncthreads();
      if (gh == 0) {
        float p = 0.f;
#pragma unroll
        for (int q = 0; q < 8; q++) p += sA[((q<<5) + b_i)*9 + d_i];
        g_logits[b*Dz + d0 + d_i] = p + bcj;
      }
    }
    grid_bar(++bgen);

    // ================= phase 4: write LSTM (softmax(x) fused) =================
    {
      const float4* Lg = (const float4*)g_logits;
      const float4* Hw = (const float4*)hwp;
      float4* A4 = (float4*)sA;
      for (int idx = tid; idx < 4096; idx += NT) {
        int r = idx >> 7, c = idx & 127;
        if (c < 64) {
          A4[r*129 + c] = Lg[(size_t)(b0+r)*64 + c];            // raw logits (softmaxed below)
        } else {
          A4[r*129 + c] = tf32r4(Hw[(size_t)(b0+r)*64 + (c-64)]);
        }
      }
      __syncthreads();
      // per-row softmax of logits half: 16 warps x 2 rows, 16 lanes per row
      {
        const int lane = tid & 31, w = tid >> 5;
        const int row = (w << 1) + (lane >> 4);
        const int sub = lane & 15;
        float* Arow = sA + row*SAS;
        float mx = -INFINITY;
        for (int k = sub; k < 256; k += 16) mx = fmaxf(mx, Arow[k]);
        mx = fmaxf(mx, __shfl_xor_sync(0xffffffffu, mx, 8));
        mx = fmaxf(mx, __shfl_xor_sync(0xffffffffu, mx, 4));
        mx = fmaxf(mx, __shfl_xor_sync(0xffffffffu, mx, 2));
        mx = fmaxf(mx, __shfl_xor_sync(0xffffffffu, mx, 1));
        float sv = 0.f;
        for (int k = sub; k < 256; k += 16) { float e = expf(Arow[k]-mx); Arow[k] = e; sv += e; }
        sv += __shfl_xor_sync(0xffffffffu, sv, 8);
        sv += __shfl_xor_sync(0xffffffffu, sv, 4);
        sv += __shfl_xor_sync(0xffffffffu, sv, 2);
        sv += __shfl_xor_sync(0xffffffffu, sv, 1);
        float inv = 1.f / sv;
        for (int k = sub; k < 256; k += 16) Arow[k] = tf32r(Arow[k] * inv);
      }
      __syncthreads();
      float accA, accB;
      gemm_lstm(sA, sWw, sA, tid, cell, gh, accA, accB);
      if (gh == 1) {
        sXc[cell*2]   = tanhf(accA + bwA);
        sXc[cell*2+1] = sigm(accB + bwB);
      }
      __syncthreads();
      if (gh == 0) {
        float ig = sigm(accA + bwA);
        float fg = sigm(accB + bwB);
        float gg = sXc[cell*2];
        float og = sXc[cell*2+1];
        cw_reg = fmaf(fg, cw_reg, ig*gg);
        float hv = og * tanhf(cw_reg);
        hwc[b*Dz + d] = hv;
        out[(size_t)t*BD + b*Dz + d] = hv;
      }
    }
    // NO grid barrier here: hw/out written in phase 4 are first consumed
    // cross-CTA only after the next step's phase-1 barrier.
  }
  grid_bar(++bgen);   // make final-step hw/hr visible for the epilogue

  // ================= final: states + M materialization =================
  if (tid < 256) {
    int i = cta*256 + tid;
    out[1048576 + i]         = g_hr[BD + i];   // hr (buf 1, t=31)
    out[1048576 + 65536 + i] = g_hw[BD + i];   // hw
  }
  if (gh == 0) {
    out[1048576 + 32768 + b*Dz + d] = cr_reg;  // cr
    out[1048576 + 98304 + b*Dz + d] = cw_reg;  // cw
  }
  {
    if (tid < 256) sHw[tid] = g_hw[BD + bown*Dz + tid];
    __syncthreads();
    const int dcol = tid & 255;
    float hwv = sHw[dcol];
    float* Mo = out + 1179648 + (size_t)bown*Lz*Dz;
    const int l0 = gh << 9;
#pragma unroll 4
    for (int l = l0; l < l0 + 512; l++) {
      float zv = sZ[l];
      Mo[(size_t)l*Dz + dcol] = (1.f - zv) + hwv*zv;
    }
  }
}

// ---------------- zero the barrier flags before each graph replay ----------
__global__ void zero_flags(){
  g_flags[threadIdx.x*32 + blockIdx.x] = 0u;
}

// ---------------- launch ----------------
extern "C" void kernel_launch(void* const* d_in, const int* in_sizes, int n_in,
                              void* d_out, int out_size)
{
  const float* emb   = (const float*)d_in[0];
  const float* hr0   = (const float*)d_in[1];
  const float* cr0   = (const float*)d_in[2];
  const float* hw0   = (const float*)d_in[3];
  const float* cw0   = (const float*)d_in[4];
  const float* M     = (const float*)d_in[5];
  const int*   mask  = (const int*)d_in[6];
  const float* Wih_r = (const float*)d_in[7];
  const float* Whh_r = (const float*)d_in[8];
  const float* bih_r = (const float*)d_in[9];
  const float* bhh_r = (const float*)d_in[10];
  const float* Wc    = (const float*)d_in[11];
  const float* bc    = (const float*)d_in[12];
  const float* Wih_w = (const float*)d_in[13];
  const float* Whh_w = (const float*)d_in[14];
  const float* bih_w = (const float*)d_in[15];
  const float* bhh_w = (const float*)d_in[16];
  float* out = (float*)d_out;

  zero_flags<<<32, NCTA>>>();

  cudaFuncSetAttribute(mega, cudaFuncAttributeMaxDynamicSharedMemorySize, SMEM_BYTES);
  mega<<<NCTA, NT, SMEM_BYTES>>>(emb, hr0, cr0, hw0, cw0, M, mask,
                                 Wih_r, Whh_r, bih_r, bhh_r, Wc, bc,
                                 Wih_w, Whh_w, bih_w, bhh_w, out);
}

// round 10
// speedup vs baseline: 2.2402x; 1.0789x over previous
#include <cuda_runtime.h>
#include <math.h>

#define NCTA 128
#define NT 512
#define Bz 128
#define Lz 1024
#define Dz 256
#define Tz 32
#define BD (Bz*Dz)      /* 32768 */
#define SAS 516

// smem layout (float offsets)
#define OFF_WR 0        /* 32x516 = 16512 */
#define OFF_WW 16512    /* 16512 */
#define OFF_WC 33024    /* 8x516 = 4128 */
#define OFF_A  37152    /* 32x516 = 16512 (also reused as partial buffer) */
#define OFF_Z  53664    /* 1024 */
#define OFF_HR 54688    /* 256 */
#define OFF_HW 54944    /* 256 */
#define OFF_RED 55200   /* 32 (two banks of 16) */
#define OFF_XC 55232    /* 512 */
#define OFF_MASK 55744  /* 256 floats = 1024 bytes */
#define SMEM_FLOATS 56000
#define SMEM_BYTES (SMEM_FLOATS*4)

// ---------------- scratch (device globals; no allocation) ----------------
__device__ float g_hr[2*BD];
__device__ float g_hw[2*BD];
__device__ float g_m[BD];
__device__ float g_L1[BD];        // comp logits part 1 (hr . Wc1^T); also raw logits at t0
__device__ float g_L2[BD];        // comp logits part 2 (hw_prev . Wc2^T)
__device__ float g_S[Bz];
__device__ float g_wcsum[Dz];     // sum_k Wc[j, 256+k]
__device__ unsigned g_flags[NCTA*32];   // one flag per CTA, 128B padded

// ---------------- helpers ----------------
__device__ __forceinline__ float warp_sum(float v){
#pragma unroll
  for (int o=16;o;o>>=1) v += __shfl_xor_sync(0xffffffffu,v,o);
  return v;
}
__device__ __forceinline__ float block_sum(float v, float* sbuf){
  v = warp_sum(v);
  int lane = threadIdx.x & 31, w = threadIdx.x >> 5;
  __syncthreads();
  if (lane == 0) sbuf[w] = v;
  __syncthreads();
  float r = sbuf[0];
#pragma unroll
  for (int i=1;i<16;i++) r += sbuf[i];
  return r;
}
__device__ __forceinline__ void block_sum2(float a, float b, float* sbuf,
                                           float& ra, float& rb){
  a = warp_sum(a); b = warp_sum(b);
  int lane = threadIdx.x & 31, w = threadIdx.x >> 5;
  __syncthreads();
  if (lane == 0) { sbuf[w] = a; sbuf[16 + w] = b; }
  __syncthreads();
  float xa = sbuf[0], xb = sbuf[16];
#pragma unroll
  for (int i=1;i<16;i++) { xa += sbuf[i]; xb += sbuf[16 + i]; }
  ra = xa; rb = xb;
}
__device__ __forceinline__ float block_max(float v, float* sbuf){
#pragma unroll
  for (int o=16;o;o>>=1) v = fmaxf(v, __shfl_xor_sync(0xffffffffu,v,o));
  int lane = threadIdx.x & 31, w = threadIdx.x >> 5;
  __syncthreads();
  if (lane == 0) sbuf[w] = v;
  __syncthreads();
  float r = sbuf[0];
#pragma unroll
  for (int i=1;i<16;i++) r = fmaxf(r, sbuf[i]);
  return r;
}
__device__ __forceinline__ float sigm(float x){ return 1.f/(1.f+expf(-x)); }

__device__ __forceinline__ float tf32r(float x){
  unsigned u;
  asm("cvt.rna.tf32.f32 %0, %1;" : "=r"(u) : "f"(x));
  return __uint_as_float(u);
}
__device__ __forceinline__ float4 tf32r4(float4 v){
  v.x = tf32r(v.x); v.y = tf32r(v.y); v.z = tf32r(v.z); v.w = tf32r(v.w);
  return v;
}

// Contention-free grid barrier (R7 pattern, unchanged).
__device__ __forceinline__ void grid_bar(unsigned gen){
  __syncthreads();
  if (threadIdx.x == 0) {
    __threadfence();                                   // release
    *(volatile unsigned*)&g_flags[blockIdx.x*32] = gen;
  }
  if (threadIdx.x < NCTA) {
    while (*(volatile unsigned*)&g_flags[threadIdx.x*32] < gen) { }
  }
  __syncthreads();
  if (threadIdx.x == 0) __threadfence();               // acquire + L1 inval
  __syncthreads();
}

#define MMA_TF32(c0,c1,c2,c3,a0,a1,a2,a3,b0,b1) \
  asm volatile("mma.sync.aligned.m16n8k8.row.col.f32.tf32.tf32.f32 " \
    "{%0,%1,%2,%3}, {%4,%5,%6,%7}, {%8,%9}, {%0,%1,%2,%3};" \
    : "+f"(c0),"+f"(c1),"+f"(c2),"+f"(c3) \
    : "r"(a0),"r"(a1),"r"(a2),"r"(a3),"r"(b0),"r"(b1))

// LSTM GEMM via tf32 mma: C[32b x 32j] = A[32 x 512] * W[32 x 512]^T.
// 16 warps = mt(2 m16) x ntt(2 n16) x kh(4 k128). sP may alias sA.
__device__ __forceinline__ void gemm_lstm(
    const float* sA, const float* sW, float* sP,
    int tid, int cell, int gh, float& preA, float& preB)
{
  const int lane = tid & 31, w = tid >> 5;
  const int kh = w & 3, mt = (w >> 2) & 1, ntt = w >> 3;
  const int gid = lane >> 2, tig = lane & 3;
  const int m0 = mt << 4, n0 = ntt << 4;
  const int kb = kh << 7;
  const float* A0 = sA + (m0 + gid)*SAS + kb + tig;
  const float* A1 = A0 + 8*SAS;
  const float* B0 = sW + (n0 + gid)*SAS + kb + tig;
  const float* B1 = B0 + 8*SAS;

  float c00=0.f,c01=0.f,c02=0.f,c03=0.f;
  float c10=0.f,c11=0.f,c12=0.f,c13=0.f;
#pragma unroll
  for (int i = 0; i < 16; i++) {
    const int k = i << 3;
    unsigned a0 = __float_as_uint(A0[k]);
    unsigned a1 = __float_as_uint(A1[k]);
    unsigned a2 = __float_as_uint(A0[k+4]);
    unsigned a3 = __float_as_uint(A1[k+4]);
    unsigned b0 = __float_as_uint(B0[k]);
    unsigned b1 = __float_as_uint(B0[k+4]);
    unsigned b2 = __float_as_uint(B1[k]);
    unsigned b3 = __float_as_uint(B1[k+4]);
    MMA_TF32(c00,c01,c02,c03, a0,a1,a2,a3, b0,b1);
    MMA_TF32(c10,c11,c12,c13, a0,a1,a2,a3, b2,b3);
  }
  __syncthreads();               // all sA reads complete before overwrite
  {
    float* r0p = sP + ((kh<<5) + m0 + gid)*33 + n0 + (tig<<1);
    float* r1p = r0p + 8*33;
    r0p[0] = c00; r0p[1] = c01;
    r1p[0] = c02; r1p[1] = c03;
    r0p[8] = c10; r0p[9] = c11;
    r1p[8] = c12; r1p[9] = c13;
  }
  __syncthreads();
  const int b_i = cell >> 3, d_i = cell & 7;
  const int r0 = (gh<<4) + d_i;
  const int r1 = r0 + 8;
  float pa = 0.f, pb = 0.f;
#pragma unroll
  for (int q = 0; q < 4; q++) {
    const float* row = sP + ((q<<5) + b_i)*33;
    pa += row[r0];
    pb += row[r1];
  }
  preA = pa; preB = pb;
}

// ---------------- the persistent mega-kernel ----------------
__global__ __launch_bounds__(NT,1) void mega(
  const float* __restrict__ emb, const float* __restrict__ hr0,
  const float* __restrict__ cr0, const float* __restrict__ hw0,
  const float* __restrict__ cw0, const float* __restrict__ M,
  const int* __restrict__ mask,
  const float* __restrict__ Wih_r, const float* __restrict__ Whh_r,
  const float* __restrict__ bih_r, const float* __restrict__ bhh_r,
  const float* __restrict__ Wc,    const float* __restrict__ bc,
  const float* __restrict__ Wih_w, const float* __restrict__ Whh_w,
  const float* __restrict__ bih_w, const float* __restrict__ bhh_w,
  float* __restrict__ out)
{
  extern __shared__ __align__(16) float sm[];
  float* sWr = sm + OFF_WR;
  float* sWw = sm + OFF_WW;
  float* sWc = sm + OFF_WC;
  float* sA  = sm + OFF_A;
  float* sZ  = sm + OFF_Z;
  float* sHr = sm + OFF_HR;
  float* sHw = sm + OFF_HW;
  float* sRed = sm + OFF_RED;
  float* sXc = sm + OFF_XC;
  unsigned char* sMask = (unsigned char*)(sm + OFF_MASK);

  const int tid = threadIdx.x;
  const int cta = blockIdx.x;
  const int jb = cta >> 2;          // 0..31
  const int bb = cta & 3;           // 0..3
  const int b0 = bb << 5;           // 32 batch rows
  const int d0 = jb << 3;           // 8 d-cols (also comp j-rows)
  const int cell = tid & 255;
  const int b_i = cell >> 3, d_i = cell & 7;
  const int gh = tid >> 8;          // gate-half
  const int b = b0 + b_i, d = d0 + d_i;
  const int bown = cta;
  const int g0 = gh*2, g1 = gh*2 + 1;
  unsigned bgen = 0;

  // ---- one-time staging ----
  {
    const float4* Wi = (const float4*)Wih_r;
    const float4* Wh = (const float4*)Whh_r;
    float4* W4 = (float4*)sWr;
    for (int idx = tid; idx < 4096; idx += NT) {
      int r = idx >> 7, c = idx & 127;
      int j = ((r >> 3) << 8) + d0 + (r & 7);
      float4 v = (c < 64) ? Wi[(size_t)j*64 + c] : Wh[(size_t)j*64 + (c-64)];
      W4[r*129 + c] = tf32r4(v);
    }
  }
  {
    const float4* Wi = (const float4*)Wih_w;
    const float4* Wh = (const float4*)Whh_w;
    float4* W4 = (float4*)sWw;
    for (int idx = tid; idx < 4096; idx += NT) {
      int r = idx >> 7, c = idx & 127;
      int j = ((r >> 3) << 8) + d0 + (r & 7);
      float4 v = (c < 64) ? Wi[(size_t)j*64 + c] : Wh[(size_t)j*64 + (c-64)];
      W4[r*129 + c] = tf32r4(v);
    }
  }
  {
    const float4* Wc4 = (const float4*)Wc;
    float4* W4 = (float4*)sWc;
    for (int idx = tid; idx < 1024; idx += NT) {
      int r = idx >> 7, c = idx & 127;
      W4[r*129 + c] = tf32r4(Wc4[(size_t)(d0 + r)*128 + c]);
    }
  }
  for (int l = tid; l < Lz; l += NT) sMask[l] = (unsigned char)(mask[bown*Lz + l] != 0);

  const float brA = bih_r[g0*256 + d] + bhh_r[g0*256 + d];
  const float brB = bih_r[g1*256 + d] + bhh_r[g1*256 + d];
  const float bwA = bih_w[g0*256 + d] + bhh_w[g0*256 + d];
  const float bwB = bih_w[g1*256 + d] + bhh_w[g1*256 + d];
  const float bcj = bc[d0 + d_i];
  float cr_reg = (gh == 0) ? cr0[b*Dz + d] : 0.f;
  float cw_reg = (gh == 0) ? cw0[b*Dz + d] : 0.f;
  __syncthreads();

  // wcsum[j] = sum_{k=256..511} Wc[j,k], from the staged (tf32) sWc.
  // Only bb==0 CTAs write (disjoint jb ranges). Note: sWc is tf32-rounded,
  // matching the tf32 gemm that produces the other logits terms.
  if (bb == 0 && tid < 64) {
    int r = tid >> 3, seg = tid & 7;
    const float* row = sWc + r*SAS + 256 + seg*32;
    float s = 0.f;
#pragma unroll
    for (int i = 0; i < 32; i++) s += row[i];
    s += __shfl_xor_sync(0xffffffffu, s, 1);
    s += __shfl_xor_sync(0xffffffffu, s, 2);
    s += __shfl_xor_sync(0xffffffffu, s, 4);
    if (seg == 0) g_wcsum[d0 + r] = s;
  }

  for (int t = 0; t < Tz; t++) {
    const int cur = t & 1;
    const float* hin = (t == 0) ? hr0 : g_hr + (cur^1)*BD;
    const float* hwp = (t == 0) ? hw0 : g_hw + (cur^1)*BD;
    float* hrc = g_hr + cur*BD;
    float* hwc = g_hw + cur*BD;

    // ================= epoch A: read LSTM =================
    {
      const float4* X = (const float4*)(emb + (size_t)t*BD);
      const float4* H = (const float4*)hin;
      float4* A4 = (float4*)sA;
      for (int idx = tid; idx < 4096; idx += NT) {
        int r = idx >> 7, c = idx & 127;
        float4 v = (c < 64) ? X[(size_t)(b0+r)*64 + c] : H[(size_t)(b0+r)*64 + (c-64)];
        A4[r*129 + c] = tf32r4(v);
      }
      __syncthreads();
      float accA, accB;
      gemm_lstm(sA, sWr, sA, tid, cell, gh, accA, accB);
      if (gh == 1) {
        sXc[cell*2]   = tanhf(accA + brA);
        sXc[cell*2+1] = sigm(accB + brB);
      }
      __syncthreads();
      if (gh == 0) {
        float ig = sigm(accA + brA);
        float fg = sigm(accB + brB);
        float gg = sXc[cell*2];
        float og = sXc[cell*2+1];
        cr_reg = fmaf(fg, cr_reg, ig*gg);
        hrc[b*Dz + d] = og * tanhf(cr_reg);
      }
    }
    grid_bar(++bgen);

    if (t == 0) {
      // ============ t0 epoch: full attention over M ============
      {
        if (tid < 256) sHr[tid] = hrc[bown*Dz + tid];
        __syncthreads();
        const int w = tid >> 5, lane = tid & 31;
        for (int l = w; l < Lz; l += 16) {
          const float* Mr = M + ((size_t)bown*Lz + l)*Dz;
          float s = 0.f;
#pragma unroll
          for (int u = 0; u < 8; u++) s = fmaf(Mr[lane + (u<<5)], sHr[lane + (u<<5)], s);
          s = warp_sum(s);
          if (lane == 0) sZ[l] = s;
        }
        __syncthreads();
        float raw[2]; float lmax = -INFINITY;
#pragma unroll
        for (int u = 0; u < 2; u++) {
          int l = tid + (u << 9);
          raw[u] = sMask[l] ? -INFINITY : sZ[l];
          lmax = fmaxf(lmax, raw[u]);
        }
        float gmax = block_max(lmax, sRed);
        float e[2]; float lsum = 0.f;
#pragma unroll
        for (int u = 0; u < 2; u++) { e[u] = expf(raw[u] - gmax); lsum += e[u]; }
        float gsum = block_sum(lsum, sRed);
        float inv = 1.f / gsum;
        __syncthreads();
#pragma unroll
        for (int u = 0; u < 2; u++) sZ[tid + (u << 9)] = e[u]*inv;
        __syncthreads();
        const int q = tid >> 6, dq = tid & 63;
        const float4* M4 = (const float4*)M;
        float4 acc = make_float4(0.f,0.f,0.f,0.f);
        const int lb = q << 7;
#pragma unroll 4
        for (int l = lb; l < lb + 128; l++) {
          float zv = sZ[l];
          float4 Mv = M4[((size_t)bown*Lz + l)*64 + dq];
          acc.x = fmaf(zv, Mv.x, acc.x);
          acc.y = fmaf(zv, Mv.y, acc.y);
          acc.z = fmaf(zv, Mv.z, acc.z);
          acc.w = fmaf(zv, Mv.w, acc.w);
        }
        ((float4*)sA)[q*64 + dq] = acc;
        __syncthreads();
        if (tid < 256) {
          float s = 0.f;
#pragma unroll
          for (int q2 = 0; q2 < 8; q2++) s += sA[q2*256 + tid];
          g_m[bown*Dz + tid] = s;
        }
      }
      grid_bar(++bgen);

      // ============ t0 comp gemm: [hr|m] @ Wc^T -> g_L1 (full logits) ============
      {
        const float4* Hc = (const float4*)hrc;
        const float4* Mm = (const float4*)g_m;
        float4* A4 = (float4*)sA;
        for (int idx = tid; idx < 4096; idx += NT) {
          int r = idx >> 7, c = idx & 127;
          float4 v = (c < 64) ? Hc[(size_t)(b0+r)*64 + c] : Mm[(size_t)(b0+r)*64 + (c-64)];
          A4[r*129 + c] = tf32r4(v);
        }
        __syncthreads();
        {
          const int lane = tid & 31, w = tid >> 5;
          const int mt = w & 1, kh = w >> 1;
          const int gid = lane >> 2, tig = lane & 3;
          const int m0 = mt << 4;
          const int kb = kh << 6;
          const float* A0 = sA + (m0 + gid)*SAS + kb + tig;
          const float* A1 = A0 + 8*SAS;
          const float* B0 = sWc + gid*SAS + kb + tig;
          float c0=0.f,c1=0.f,c2=0.f,c3=0.f;
#pragma unroll
          for (int i = 0; i < 8; i++) {
            const int k = i << 3;
            unsigned a0 = __float_as_uint(A0[k]);
            unsigned a1 = __float_as_uint(A1[k]);
            unsigned a2 = __float_as_uint(A0[k+4]);
            unsigned a3 = __float_as_uint(A1[k+4]);
            unsigned b0r = __float_as_uint(B0[k]);
            unsigned b1r = __float_as_uint(B0[k+4]);
            MMA_TF32(c0,c1,c2,c3, a0,a1,a2,a3, b0r,b1r);
          }
          __syncthreads();
          float* r0p = sA + ((kh<<5) + m0 + gid)*9 + (tig<<1);
          float* r1p = r0p + 8*9;
          r0p[0] = c0; r0p[1] = c1;
          r1p[0] = c2; r1p[1] = c3;
        }
        __syncthreads();
        if (gh == 0) {
          float p = 0.f;
#pragma unroll
          for (int q = 0; q < 8; q++) p += sA[((q<<5) + b_i)*9 + d_i];
          g_L1[b*Dz + d0 + d_i] = p + bcj;
        }
      }
      grid_bar(++bgen);

      // ============ t0 write LSTM (stage raw logits + hw0) ============
      {
        const float4* Lg = (const float4*)g_L1;
        const float4* Hw = (const float4*)hwp;
        float4* A4 = (float4*)sA;
        for (int idx = tid; idx < 4096; idx += NT) {
          int r = idx >> 7, c = idx & 127;
          if (c < 64) A4[r*129 + c] = Lg[(size_t)(b0+r)*64 + c];
          else        A4[r*129 + c] = tf32r4(Hw[(size_t)(b0+r)*64 + (c-64)]);
        }
        __syncthreads();
        {
          const int lane = tid & 31, w = tid >> 5;
          const int row = (w << 1) + (lane >> 4);
          const int sub = lane & 15;
          float* Arow = sA + row*SAS;
          float mx = -INFINITY;
          for (int k = sub; k < 256; k += 16) mx = fmaxf(mx, Arow[k]);
          mx = fmaxf(mx, __shfl_xor_sync(0xffffffffu, mx, 8));
          mx = fmaxf(mx, __shfl_xor_sync(0xffffffffu, mx, 4));
          mx = fmaxf(mx, __shfl_xor_sync(0xffffffffu, mx, 2));
          mx = fmaxf(mx, __shfl_xor_sync(0xffffffffu, mx, 1));
          float sv = 0.f;
          for (int k = sub; k < 256; k += 16) { float e = expf(Arow[k]-mx); Arow[k] = e; sv += e; }
          sv += __shfl_xor_sync(0xffffffffu, sv, 8);
          sv += __shfl_xor_sync(0xffffffffu, sv, 4);
          sv += __shfl_xor_sync(0xffffffffu, sv, 2);
          sv += __shfl_xor_sync(0xffffffffu, sv, 1);
          float inv = 1.f / sv;
          for (int k = sub; k < 256; k += 16) Arow[k] = tf32r(Arow[k] * inv);
        }
        __syncthreads();
        float accA, accB;
        gemm_lstm(sA, sWw, sA, tid, cell, gh, accA, accB);
        if (gh == 1) {
          sXc[cell*2]   = tanhf(accA + bwA);
          sXc[cell*2+1] = sigm(accB + bwB);
        }
        __syncthreads();
        if (gh == 0) {
          float ig = sigm(accA + bwA);
          float fg = sigm(accB + bwB);
          float gg = sXc[cell*2];
          float og = sXc[cell*2+1];
          cw_reg = fmaf(fg, cw_reg, ig*gg);
          float hv = og * tanhf(cw_reg);
          hwc[b*Dz + d] = hv;
          out[(size_t)t*BD + b*Dz + d] = hv;
        }
      }
      // no barrier (protected by next step's epoch-A barrier)
    } else {
      // ============ epoch B: attention + L1/L2 gemms ============
      {
        // stage sA = [tf32(hr) | tf32(hw_prev)] rows (loads overlap attention)
        {
          const float4* Hc = (const float4*)hrc;
          const float4* Hw = (const float4*)hwp;
          float4* A4 = (float4*)sA;
          for (int idx = tid; idx < 4096; idx += NT) {
            int r = idx >> 7, c = idx & 127;
            float4 v = (c < 64) ? Hc[(size_t)(b0+r)*64 + c] : Hw[(size_t)(b0+r)*64 + (c-64)];
            A4[r*129 + c] = tf32r4(v);
          }
        }
        if (tid < 256) { sHr[tid] = hrc[bown*Dz + tid]; sHw[tid] = hwp[bown*Dz + tid]; }
        __syncthreads();
        float hrv = (tid < 256) ? sHr[tid] : 0.f;
        float hwv = (tid < 256) ? sHw[tid] : 0.f;
        float Shr, dot;
        block_sum2(hrv, hrv*hwv, sRed, Shr, dot);
        float alpha = dot - Shr;
        float zp[2], raw[2]; float lmax = -INFINITY;
#pragma unroll
        for (int u = 0; u < 2; u++) {
          int l = tid + (u << 9);
          zp[u] = sZ[l];
          raw[u] = sMask[l] ? -INFINITY : fmaf(zp[u], alpha, Shr);
          lmax = fmaxf(lmax, raw[u]);
        }
        float gmax = block_max(lmax, sRed);
        float e[2]; float lsum = 0.f, lt = 0.f;
#pragma unroll
        for (int u = 0; u < 2; u++) { e[u] = expf(raw[u] - gmax); lsum += e[u]; lt += e[u]*zp[u]; }
        float gsum, gt;
        block_sum2(lsum, lt, sRed, gsum, gt);
        float inv = 1.f / gsum;
        __syncthreads();
#pragma unroll
        for (int u = 0; u < 2; u++) sZ[tid + (u << 9)] = e[u]*inv;
        float S = gt * inv;
        if (tid == 0) g_S[bown] = S;
        __syncthreads();   // sA staging + sZ done before gemm reads

        // L1/L2 gemms: 16 warps = g(2) x mt(2) x kh(4 of k64). C = 32b x 8j each.
        {
          const int lane = tid & 31, w = tid >> 5;
          const int g = w >> 3, w7 = w & 7;
          const int mt = w7 & 1, kh = w7 >> 1;
          const int gid = lane >> 2, tig = lane & 3;
          const int m0 = mt << 4;
          const int kb = (g << 8) + (kh << 6);
          const float* A0 = sA + (m0 + gid)*SAS + kb + tig;
          const float* A1 = A0 + 8*SAS;
          const float* B0 = sWc + gid*SAS + kb + tig;
          float c0=0.f,c1=0.f,c2=0.f,c3=0.f;
#pragma unroll
          for (int i = 0; i < 8; i++) {
            const int k = i << 3;
            unsigned a0 = __float_as_uint(A0[k]);
            unsigned a1 = __float_as_uint(A1[k]);
            unsigned a2 = __float_as_uint(A0[k+4]);
            unsigned a3 = __float_as_uint(A1[k+4]);
            unsigned b0r = __float_as_uint(B0[k]);
            unsigned b1r = __float_as_uint(B0[k+4]);
            MMA_TF32(c0,c1,c2,c3, a0,a1,a2,a3, b0r,b1r);
          }
          __syncthreads();   // all sA reads complete before partial overwrite
          float* r0p = sA + ((g*4 + kh)*288) + (m0 + gid)*9 + (tig<<1);
          float* r1p = r0p + 8*9;
          r0p[0] = c0; r0p[1] = c1;
          r1p[0] = c2; r1p[1] = c3;
        }
        __syncthreads();
        if (gh == 0) {
          float l1 = 0.f, l2 = 0.f;
#pragma unroll
          for (int q = 0; q < 4; q++) {
            l1 += sA[q*288       + b_i*9 + d_i];
            l2 += sA[(4+q)*288   + b_i*9 + d_i];
          }
          g_L1[b*Dz + d0 + d_i] = l1;
          g_L2[b*Dz + d0 + d_i] = l2;
        }
      }
      grid_bar(++bgen);

      // ============ epoch C: assemble logits + softmax + write LSTM ============
      {
        const float4* L14 = (const float4*)g_L1;
        const float4* L24 = (const float4*)g_L2;
        const float4* WS4 = (const float4*)g_wcsum;
        const float4* BC4 = (const float4*)bc;
        const float4* Hw  = (const float4*)hwp;
        float4* A4 = (float4*)sA;
        for (int idx = tid; idx < 4096; idx += NT) {
          int r = idx >> 7, c = idx & 127;
          if (c < 64) {
            float Sb = g_S[b0 + r];
            float4 l1 = L14[(size_t)(b0+r)*64 + c];
            float4 l2 = L24[(size_t)(b0+r)*64 + c];
            float4 wsv = WS4[c];
            float4 bcv = BC4[c];
            float4 o;
            o.x = l1.x + Sb*l2.x + (1.f-Sb)*wsv.x + bcv.x;
            o.y = l1.y + Sb*l2.y + (1.f-Sb)*wsv.y + bcv.y;
            o.z = l1.z + Sb*l2.z + (1.f-Sb)*wsv.z + bcv.z;
            o.w = l1.w + Sb*l2.w + (1.f-Sb)*wsv.w + bcv.w;
            A4[r*129 + c] = o;
          } else {
            A4[r*129 + c] = tf32r4(Hw[(size_t)(b0+r)*64 + (c-64)]);
          }
        }
        __syncthreads();
        {
          const int lane = tid & 31, w = tid >> 5;
          const int row = (w << 1) + (lane >> 4);
          const int sub = lane & 15;
          float* Arow = sA + row*SAS;
          float mx = -INFINITY;
          for (int k = sub; k < 256; k += 16) mx = fmaxf(mx, Arow[k]);
          mx = fmaxf(mx, __shfl_xor_sync(0xffffffffu, mx, 8));
          mx = fmaxf(mx, __shfl_xor_sync(0xffffffffu, mx, 4));
          mx = fmaxf(mx, __shfl_xor_sync(0xffffffffu, mx, 2));
          mx = fmaxf(mx, __shfl_xor_sync(0xffffffffu, mx, 1));
          float sv = 0.f;
          for (int k = sub; k < 256; k += 16) { float e = expf(Arow[k]-mx); Arow[k] = e; sv += e; }
          sv += __shfl_xor_sync(0xffffffffu, sv, 8);
          sv += __shfl_xor_sync(0xffffffffu, sv, 4);
          sv += __shfl_xor_sync(0xffffffffu, sv, 2);
          sv += __shfl_xor_sync(0xffffffffu, sv, 1);
          float inv = 1.f / sv;
          for (int k = sub; k < 256; k += 16) Arow[k] = tf32r(Arow[k] * inv);
        }
        __syncthreads();
        float accA, accB;
        gemm_lstm(sA, sWw, sA, tid, cell, gh, accA, accB);
        if (gh == 1) {
          sXc[cell*2]   = tanhf(accA + bwA);
          sXc[cell*2+1] = sigm(accB + bwB);
        }
        __syncthreads();
        if (gh == 0) {
          float ig = sigm(accA + bwA);
          float fg = sigm(accB + bwB);
          float gg = sXc[cell*2];
          float og = sXc[cell*2+1];
          cw_reg = fmaf(fg, cw_reg, ig*gg);
          float hv = og * tanhf(cw_reg);
          hwc[b*Dz + d] = hv;
          out[(size_t)t*BD + b*Dz + d] = hv;
        }
      }
      // no barrier (next epoch A reads nothing written here)
    }
  }
  grid_bar(++bgen);   // make final-step hw/hr visible for the epilogue

  // ================= final: states + M materialization =================
  if (tid < 256) {
    int i = cta*256 + tid;
    out[1048576 + i]         = g_hr[BD + i];   // hr (buf 1, t=31)
    out[1048576 + 65536 + i] = g_hw[BD + i];   // hw
  }
  if (gh == 0) {
    out[1048576 + 32768 + b*Dz + d] = cr_reg;  // cr
    out[1048576 + 98304 + b*Dz + d] = cw_reg;  // cw
  }
  {
    if (tid < 256) sHw[tid] = g_hw[BD + bown*Dz + tid];
    __syncthreads();
    const int dcol = tid & 255;
    float hwv = sHw[dcol];
    float* Mo = out + 1179648 + (size_t)bown*Lz*Dz;
    const int l0 = gh << 9;
#pragma unroll 4
    for (int l = l0; l < l0 + 512; l++) {
      float zv = sZ[l];
      Mo[(size_t)l*Dz + dcol] = (1.f - zv) + hwv*zv;
    }
  }
}

// ---------------- zero the barrier flags before each graph replay ----------
__global__ void zero_flags(){
  g_flags[threadIdx.x*32 + blockIdx.x] = 0u;
}

// ---------------- launch ----------------
extern "C" void kernel_launch(void* const* d_in, const int* in_sizes, int n_in,
                              void* d_out, int out_size)
{
  const float* emb   = (const float*)d_in[0];
  const float* hr0   = (const float*)d_in[1];
  const float* cr0   = (const float*)d_in[2];
  const float* hw0   = (const float*)d_in[3];
  const float* cw0   = (const float*)d_in[4];
  const float* M     = (const float*)d_in[5];
  const int*   mask  = (const int*)d_in[6];
  const float* Wih_r = (const float*)d_in[7];
  const float* Whh_r = (const float*)d_in[8];
  const float* bih_r = (const float*)d_in[9];
  const float* bhh_r = (const float*)d_in[10];
  const float* Wc    = (const float*)d_in[11];
  const float* bc    = (const float*)d_in[12];
  const float* Wih_w = (const float*)d_in[13];
  const float* Whh_w = (const float*)d_in[14];
  const float* bih_w = (const float*)d_in[15];
  const float* bhh_w = (const float*)d_in[16];
  float* out = (float*)d_out;

  zero_flags<<<32, NCTA>>>();

  cudaFuncSetAttribute(mega, cudaFuncAttributeMaxDynamicSharedMemorySize, SMEM_BYTES);
  mega<<<NCTA, NT, SMEM_BYTES>>>(emb, hr0, cr0, hw0, cw0, M, mask,
                                 Wih_r, Whh_r, bih_r, bhh_r, Wc, bc,
                                 Wih_w, Whh_w, bih_w, bhh_w, out);
}